// round 1
// baseline (speedup 1.0000x reference)
#include <cuda_runtime.h>
#include <math.h>

// ---------------- scratch (static device globals; no allocation) ----------------
__device__ float g_h  [50000 * 256];   // post-GEMM features for current layer
__device__ float g_out[50000 * 256];   // aggregated output / next-layer input
__device__ float g_as [50000 * 4];     // per-node src scores
__device__ float g_ad [50000 * 4];     // per-node dst scores
__device__ float g_m  [50000 * 4];     // segment max
__device__ float g_den[50000 * 4];     // segment sum of exp
__device__ float g_bnsum[256];
__device__ float g_bnsq [256];
__device__ float g_pool[64 * 64];
__device__ float g_cnt [64];

__device__ __forceinline__ float leaky02(float v) { return v > 0.f ? v : 0.2f * v; }

__device__ __forceinline__ void atomicMaxFloat(float* addr, float value) {
    if (value >= 0.f) atomicMax((int*)addr, __float_as_int(value));
    else              atomicMin((unsigned int*)addr, __float_as_uint(value));
}

// ---------------- generic fill ----------------
__global__ void fill_kernel(float* p, float v, int n) {
    int i = blockIdx.x * blockDim.x + threadIdx.x;
    if (i < n) p[i] = v;
}

// per-layer init: segment max/den, bn accumulators, pool accumulators
__global__ void init_layer_kernel(int nm) {
    int i = blockIdx.x * blockDim.x + threadIdx.x;
    if (i < nm) { g_m[i] = -INFINITY; g_den[i] = 0.f; }
    if (i < 256) { g_bnsum[i] = 0.f; g_bnsq[i] = 0.f; }
    if (i < 64 * 64) g_pool[i] = 0.f;
    if (i < 64) g_cnt[i] = 0.f;
}

// ---------------- GEMM: C[N,K] = A[N,M] @ B[M,K], 64x64 tile, 4x4/thread ----------------
__global__ __launch_bounds__(256) void gemm64_kernel(
    const float* __restrict__ A, const float* __restrict__ B, float* __restrict__ C,
    int N, int M, int K)
{
    __shared__ float As[16][65];
    __shared__ float Bs[16][65];
    int block_row = blockIdx.y * 64;
    int block_col = blockIdx.x * 64;
    int tx = threadIdx.x, ty = threadIdx.y;
    int tid = ty * 16 + tx;
    float acc[4][4] = {};
    for (int k0 = 0; k0 < M; k0 += 16) {
        #pragma unroll
        for (int s = 0; s < 4; s++) {
            int i = tid + s * 256;
            int m = i >> 4, kk = i & 15;
            int gr = block_row + m;
            As[kk][m] = (gr < N) ? A[(size_t)gr * M + k0 + kk] : 0.f;
        }
        #pragma unroll
        for (int s = 0; s < 4; s++) {
            int i = tid + s * 256;
            int kk = i >> 6, n = i & 63;
            Bs[kk][n] = B[(size_t)(k0 + kk) * K + block_col + n];
        }
        __syncthreads();
        #pragma unroll
        for (int kk = 0; kk < 16; kk++) {
            float ra[4], rb[4];
            #pragma unroll
            for (int i = 0; i < 4; i++) ra[i] = As[kk][ty * 4 + i];
            #pragma unroll
            for (int j = 0; j < 4; j++) rb[j] = Bs[kk][tx * 4 + j];
            #pragma unroll
            for (int i = 0; i < 4; i++)
                #pragma unroll
                for (int j = 0; j < 4; j++) acc[i][j] += ra[i] * rb[j];
        }
        __syncthreads();
    }
    #pragma unroll
    for (int i = 0; i < 4; i++) {
        int gr = block_row + ty * 4 + i;
        if (gr < N) {
            #pragma unroll
            for (int j = 0; j < 4; j++)
                C[(size_t)gr * K + block_col + tx * 4 + j] = acc[i][j];
        }
    }
}

// ---------------- per-node attention scores ----------------
__global__ void score_kernel(const float* __restrict__ h,
                             const float* __restrict__ atts, const float* __restrict__ attd,
                             int N, int Hh, int C)
{
    int t = blockIdx.x * blockDim.x + threadIdx.x;
    if (t >= N * Hh) return;
    int n = t / Hh, hh = t - n * Hh;
    const float* row = h + (size_t)n * Hh * C + hh * C;
    float s = 0.f, d = 0.f;
    for (int c = 0; c < C; c++) {
        float v = row[c];
        s += v * atts[hh * C + c];
        d += v * attd[hh * C + c];
    }
    g_as[t] = s;
    g_ad[t] = d;
}

// ---------------- edge passes ----------------
__global__ void edge_max_kernel(const int* __restrict__ ei, int E, int N, int Hh) {
    int t = blockIdx.x * blockDim.x + threadIdx.x;
    int total = (E + N) * Hh;
    if (t >= total) return;
    int e = t / Hh, hh = t - e * Hh;
    int s, d;
    if (e < E) { s = ei[e]; d = ei[E + e]; } else { s = d = e - E; }
    float v = leaky02(g_as[s * Hh + hh] + g_ad[d * Hh + hh]);
    atomicMaxFloat(&g_m[d * Hh + hh], v);
}

__global__ void edge_sum_kernel(const int* __restrict__ ei, int E, int N, int Hh) {
    int t = blockIdx.x * blockDim.x + threadIdx.x;
    int total = (E + N) * Hh;
    if (t >= total) return;
    int e = t / Hh, hh = t - e * Hh;
    int s, d;
    if (e < E) { s = ei[e]; d = ei[E + e]; } else { s = d = e - E; }
    float v = leaky02(g_as[s * Hh + hh] + g_ad[d * Hh + hh]);
    atomicAdd(&g_den[d * Hh + hh], expf(v - g_m[d * Hh + hh]));
}

__global__ void edge_msg_kernel(const int* __restrict__ ei, int E, int N, int Hh, int C,
                                const float* __restrict__ hbuf, float* __restrict__ out)
{
    int t = blockIdx.x * blockDim.x + threadIdx.x;
    int total = (E + N) * Hh * C;
    if (t >= total) return;
    int c = t % C;
    int eh = t / C;
    int hh = eh % Hh;
    int e = eh / Hh;
    int s, d;
    if (e < E) { s = ei[e]; d = ei[E + e]; } else { s = d = e - E; }
    int sh = s * Hh + hh, dh = d * Hh + hh;
    float v = leaky02(g_as[sh] + g_ad[dh]);
    float alpha = expf(v - g_m[dh]) / (g_den[dh] + 1e-16f);
    atomicAdd(&out[(size_t)dh * C + c], hbuf[(size_t)sh * C + c] * alpha);
}

// ---------------- batch norm ----------------
__global__ void bn_stats_kernel(const float* __restrict__ x, int N, int F) {
    int f = threadIdx.x;   // blockDim.x == F
    float s = 0.f, q = 0.f;
    for (int n = blockIdx.x; n < N; n += gridDim.x) {
        float v = x[(size_t)n * F + f];
        s += v; q += v * v;
    }
    atomicAdd(&g_bnsum[f], s);
    atomicAdd(&g_bnsq[f], q);
}

__global__ void bn_elu_kernel(float* __restrict__ x, int N, int F,
                              const float* __restrict__ g, const float* __restrict__ bt)
{
    int i = blockIdx.x * blockDim.x + threadIdx.x;
    if (i >= N * F) return;
    int f = i % F;
    float inv_n = 1.0f / (float)N;
    float mu = g_bnsum[f] * inv_n;
    float var = g_bnsq[f] * inv_n - mu * mu;
    float v = (x[i] - mu) * rsqrtf(var + 1e-5f) * g[f] + bt[f];
    x[i] = v > 0.f ? v : (expf(v) - 1.f);
}

// ---------------- global mean pool ----------------
__global__ void pool_kernel(const float* __restrict__ x, const int* __restrict__ batch, int N) {
    int i = blockIdx.x * blockDim.x + threadIdx.x;
    if (i >= N * 64) return;
    int n = i >> 6, f = i & 63;
    int b = batch[n];
    atomicAdd(&g_pool[b * 64 + f], x[i]);
    if (f == 0) atomicAdd(&g_cnt[b], 1.0f);
}

// ---------------- MLP head: one block per graph ----------------
__global__ void mlp_kernel(const float* __restrict__ fw1, const float* __restrict__ fb1,
                           const float* __restrict__ fw2, const float* __restrict__ fb2,
                           const float* __restrict__ fw3, const float* __restrict__ fb3,
                           float* __restrict__ out)
{
    __shared__ float p[64], z1[128], z2[32];
    int gph = blockIdx.x;
    int t = threadIdx.x;   // 128 threads
    if (t < 64) p[t] = g_pool[gph * 64 + t] / fmaxf(g_cnt[gph], 1.0f);
    __syncthreads();
    float a = fb1[t];
    #pragma unroll 8
    for (int k = 0; k < 64; k++) a += p[k] * fw1[k * 128 + t];
    z1[t] = leaky02(a);
    __syncthreads();
    if (t < 32) {
        float b = fb2[t];
        #pragma unroll 8
        for (int k = 0; k < 128; k++) b += z1[k] * fw2[k * 32 + t];
        z2[t] = leaky02(b);
    }
    __syncthreads();
    if (t < 2) {
        float c = fb3[t];
        #pragma unroll
        for (int k = 0; k < 32; k++) c += z2[k] * fw3[k * 2 + t];
        out[gph * 2 + t] = c;
    }
}

// ---------------- host orchestration ----------------
static void run_gat_layer(const float* in, int Fin, const float* W,
                          const float* atts, const float* attd,
                          int Hh, int C, const float* g, const float* bt,
                          const int* ei, int N, int E,
                          float* hbuf, float* obuf)
{
    int HC = Hh * C;
    dim3 gb((HC + 63) / 64, (N + 63) / 64), tb(16, 16);
    gemm64_kernel<<<gb, tb>>>(in, W, hbuf, N, Fin, HC);

    int nt = N * Hh;
    score_kernel<<<(nt + 255) / 256, 256>>>(hbuf, atts, attd, N, Hh, C);

    init_layer_kernel<<<(nt + 255) / 256, 256>>>(nt);
    int nz = N * HC;
    fill_kernel<<<(nz + 255) / 256, 256>>>(obuf, 0.f, nz);

    int te = (E + N) * Hh;
    edge_max_kernel<<<(te + 255) / 256, 256>>>(ei, E, N, Hh);
    edge_sum_kernel<<<(te + 255) / 256, 256>>>(ei, E, N, Hh);
    int tm = (E + N) * HC;
    edge_msg_kernel<<<(tm + 255) / 256, 256>>>(ei, E, N, Hh, C, hbuf, obuf);

    bn_stats_kernel<<<256, HC>>>(obuf, N, HC);
    bn_elu_kernel<<<(nz + 255) / 256, 256>>>(obuf, N, HC, g, bt);
}

extern "C" void kernel_launch(void* const* d_in, const int* in_sizes, int n_in,
                              void* d_out, int out_size)
{
    const float* x     = (const float*)d_in[0];
    const int*   ei    = (const int*)  d_in[1];
    const int*   batch = (const int*)  d_in[2];
    const float* W1  = (const float*)d_in[3];
    const float* as1 = (const float*)d_in[4];
    const float* ad1 = (const float*)d_in[5];
    const float* W2  = (const float*)d_in[7];
    const float* as2 = (const float*)d_in[8];
    const float* ad2 = (const float*)d_in[9];
    const float* W3  = (const float*)d_in[11];
    const float* as3 = (const float*)d_in[12];
    const float* ad3 = (const float*)d_in[13];
    const float* g1  = (const float*)d_in[15];
    const float* bt1 = (const float*)d_in[16];
    const float* g2  = (const float*)d_in[17];
    const float* bt2 = (const float*)d_in[18];
    const float* g3  = (const float*)d_in[19];
    const float* bt3 = (const float*)d_in[20];
    const float* fw1 = (const float*)d_in[21];
    const float* fb1 = (const float*)d_in[22];
    const float* fw2 = (const float*)d_in[23];
    const float* fb2 = (const float*)d_in[24];
    const float* fw3 = (const float*)d_in[25];
    const float* fb3 = (const float*)d_in[26];

    int N = in_sizes[0] / 128;
    int E = in_sizes[1] / 2;

    float *hbuf, *obuf;
    cudaGetSymbolAddress((void**)&hbuf, g_h);
    cudaGetSymbolAddress((void**)&obuf, g_out);

    // Note: biases b1/b2/b3 are mathematically removed by the following BatchNorm
    // (per-feature constant shift cancels against the BN mean), so they are skipped.
    run_gat_layer(x,    128, W1, as1, ad1, 4, 64, g1, bt1, ei, N, E, hbuf, obuf);
    run_gat_layer(obuf, 256, W2, as2, ad2, 4, 32, g2, bt2, ei, N, E, hbuf, obuf);
    run_gat_layer(obuf, 128, W3, as3, ad3, 1, 64, g3, bt3, ei, N, E, hbuf, obuf);

    pool_kernel<<<(N * 64 + 255) / 256, 256>>>(obuf, batch, N);
    mlp_kernel<<<64, 128>>>(fw1, fb1, fw2, fb2, fw3, fb3, (float*)d_out);
}

// round 7
// speedup vs baseline: 2.9117x; 2.9117x over previous
#include <cuda_runtime.h>
#include <math.h>

// ---------------- scratch (static device globals; no allocation) ----------------
__device__ float g_h  [50000 * 256];   // post-GEMM features for current layer
__device__ float g_out[50000 * 256];   // aggregated output / next-layer input
__device__ float g_as [50000 * 4];     // per-node src scores
__device__ float g_ad [50000 * 4];     // per-node dst scores
__device__ int   g_deg[50000];
__device__ int   g_off[50001];
__device__ int   g_cur[50000];
__device__ int   g_csr[850000];        // E + N entries (src ids, grouped by dst)
__device__ float g_bnsum[256];
__device__ float g_bnsq [256];
__device__ float g_pool[64 * 64];
__device__ float g_cnt [64];

__device__ __forceinline__ float leaky02(float v) { return v > 0.f ? v : 0.2f * v; }

// ---------------- one-time init ----------------
__global__ void init_once_kernel(int N) {
    int i = blockIdx.x * blockDim.x + threadIdx.x;
    if (i < N) g_deg[i] = 0;
    if (i < 64 * 64) g_pool[i] = 0.f;
    if (i < 64) g_cnt[i] = 0.f;
}

// ---------------- CSR build ----------------
__global__ void count_kernel(const int* __restrict__ ei, int E) {
    int e = blockIdx.x * blockDim.x + threadIdx.x;
    if (e < E) atomicAdd(&g_deg[ei[E + e]], 1);
}

// single-block inclusive scan of (deg[i]+1) -> g_off[i+1]; g_off[0]=0
__global__ void scan_kernel(int N) {
    __shared__ int buf[2][1024];
    __shared__ int carry;
    if (threadIdx.x == 0) { carry = 0; g_off[0] = 0; }
    __syncthreads();
    for (int base = 0; base < N; base += 1024) {
        int i = base + threadIdx.x;
        int cur = 0;
        buf[cur][threadIdx.x] = (i < N) ? (g_deg[i] + 1) : 0;
        __syncthreads();
        for (int ofs = 1; ofs < 1024; ofs <<= 1) {
            int nxt = cur ^ 1;
            int v = buf[cur][threadIdx.x];
            if (threadIdx.x >= ofs) v += buf[cur][threadIdx.x - ofs];
            buf[nxt][threadIdx.x] = v;
            cur = nxt;
            __syncthreads();
        }
        if (i < N) g_off[i + 1] = carry + buf[cur][threadIdx.x];
        __syncthreads();
        if (threadIdx.x == 0) carry += buf[cur][1023];
        __syncthreads();
    }
}

__global__ void selfloop_kernel(int N) {
    int n = blockIdx.x * blockDim.x + threadIdx.x;
    if (n < N) {
        g_csr[g_off[n]] = n;   // self loop first
        g_cur[n] = 0;
    }
}

__global__ void scatter_kernel(const int* __restrict__ ei, int E) {
    int e = blockIdx.x * blockDim.x + threadIdx.x;
    if (e >= E) return;
    int d = ei[E + e];
    int pos = g_off[d] + 1 + atomicAdd(&g_cur[d], 1);
    g_csr[pos] = ei[e];
}

// ---------------- GEMM: C[N,K] = A[N,M] @ B[M,K]; BM=128,BN=64,BK=16, 256 thr, 8x4 ----------------
__global__ __launch_bounds__(256) void gemm_kernel(
    const float* __restrict__ A, const float* __restrict__ B, float* __restrict__ C,
    int N, int M, int K)
{
    __shared__ float As[16][132];   // As[kk][m]
    __shared__ float Bs[16][64];    // Bs[kk][n]
    int row0 = blockIdx.y * 128;
    int col0 = blockIdx.x * 64;
    int t = threadIdx.x;
    int tx = t & 15;        // 16 col groups * 4
    int ty = t >> 4;        // 16 row groups * 8
    float acc[8][4] = {};

    for (int k0 = 0; k0 < M; k0 += 16) {
        // load A tile: 512 float4, 2 per thread
        #pragma unroll
        for (int s = 0; s < 2; s++) {
            int idx = t + s * 256;
            int m = idx >> 2;
            int kk = (idx & 3) * 4;
            int gr = row0 + m;
            float4 v = make_float4(0.f, 0.f, 0.f, 0.f);
            if (gr < N) v = *(const float4*)&A[(size_t)gr * M + k0 + kk];
            As[kk + 0][m] = v.x;
            As[kk + 1][m] = v.y;
            As[kk + 2][m] = v.z;
            As[kk + 3][m] = v.w;
        }
        // load B tile: 256 float4, 1 per thread
        {
            int kk = t >> 4;
            int n = (t & 15) * 4;
            *(float4*)&Bs[kk][n] = *(const float4*)&B[(size_t)(k0 + kk) * K + col0 + n];
        }
        __syncthreads();
        #pragma unroll
        for (int kk = 0; kk < 16; kk++) {
            float4 a0 = *(const float4*)&As[kk][ty * 8];
            float4 a1 = *(const float4*)&As[kk][ty * 8 + 4];
            float4 b  = *(const float4*)&Bs[kk][tx * 4];
            float a[8] = {a0.x, a0.y, a0.z, a0.w, a1.x, a1.y, a1.z, a1.w};
            float bb[4] = {b.x, b.y, b.z, b.w};
            #pragma unroll
            for (int i = 0; i < 8; i++)
                #pragma unroll
                for (int j = 0; j < 4; j++)
                    acc[i][j] += a[i] * bb[j];
        }
        __syncthreads();
    }
    #pragma unroll
    for (int i = 0; i < 8; i++) {
        int gr = row0 + ty * 8 + i;
        if (gr < N) {
            float4 v = make_float4(acc[i][0], acc[i][1], acc[i][2], acc[i][3]);
            *(float4*)&C[(size_t)gr * K + col0 + tx * 4] = v;
        }
    }
}

// ---------------- per-node attention scores: warp per (node, head) ----------------
__global__ void score_kernel(const float* __restrict__ h,
                             const float* __restrict__ atts, const float* __restrict__ attd,
                             int N, int Hh, int C)
{
    int w = (blockIdx.x * blockDim.x + threadIdx.x) >> 5;
    int lane = threadIdx.x & 31;
    if (w >= N * Hh) return;
    int n = w / Hh, hh = w - n * Hh;
    const float* row = h + (size_t)n * Hh * C + hh * C;
    float s = 0.f, d = 0.f;
    for (int c = lane; c < C; c += 32) {
        float v = row[c];
        s += v * atts[hh * C + c];
        d += v * attd[hh * C + c];
    }
    #pragma unroll
    for (int o = 16; o; o >>= 1) {
        s += __shfl_xor_sync(0xffffffffu, s, o);
        d += __shfl_xor_sync(0xffffffffu, d, o);
    }
    if (lane == 0) { g_as[w] = s; g_ad[w] = d; }
}

// ---------------- fused online-softmax aggregation: warp per (dst, head) ----------------
template <int C>
__global__ void aggregate_kernel(const float* __restrict__ h, float* __restrict__ out,
                                 int N, int Hh)
{
    int w = (blockIdx.x * blockDim.x + threadIdx.x) >> 5;
    int lane = threadIdx.x & 31;
    if (w >= N * Hh) return;
    int dst = w / Hh, hh = w - dst * Hh;
    int beg = g_off[dst], end = g_off[dst + 1];
    float ad = g_ad[w];
    constexpr int V = C / 32;
    float acc[V];
    #pragma unroll
    for (int v = 0; v < V; v++) acc[v] = 0.f;
    float m = -INFINITY, den = 0.f;

    for (int i = beg; i < end; i++) {
        int src = g_csr[i];
        float e = leaky02(g_as[src * Hh + hh] + ad);
        float mn = fmaxf(m, e);
        float scale = __expf(m - mn);     // 0 on first iteration (m=-inf)
        float wgt = __expf(e - mn);
        den = den * scale + wgt;
        const float* hp = h + (size_t)src * (Hh * C) + hh * C + lane;
        #pragma unroll
        for (int v = 0; v < V; v++)
            acc[v] = acc[v] * scale + wgt * hp[v * 32];
        m = mn;
    }
    float inv = 1.f / (den + 1e-16f);
    float* op = out + (size_t)dst * (Hh * C) + hh * C + lane;
    #pragma unroll
    for (int v = 0; v < V; v++) op[v * 32] = acc[v] * inv;
}

// ---------------- batch norm ----------------
__global__ void bn_zero_kernel() {
    int i = threadIdx.x;
    g_bnsum[i] = 0.f;
    g_bnsq[i] = 0.f;
}

__global__ void bn_stats_kernel(const float* __restrict__ x, int N, int F) {
    int f = threadIdx.x;   // blockDim.x == F
    float s = 0.f, q = 0.f;
    for (int n = blockIdx.x; n < N; n += gridDim.x) {
        float v = x[(size_t)n * F + f];
        s += v; q += v * v;
    }
    atomicAdd(&g_bnsum[f], s);
    atomicAdd(&g_bnsq[f], q);
}

__global__ void bn_elu_kernel(float* __restrict__ x, int N, int F,
                              const float* __restrict__ g, const float* __restrict__ bt)
{
    int i = blockIdx.x * blockDim.x + threadIdx.x;
    if (i >= N * F) return;
    int f = i % F;
    float inv_n = 1.0f / (float)N;
    float mu = g_bnsum[f] * inv_n;
    float var = g_bnsq[f] * inv_n - mu * mu;
    float v = (x[i] - mu) * rsqrtf(var + 1e-5f) * g[f] + bt[f];
    x[i] = v > 0.f ? v : (expf(v) - 1.f);
}

// ---------------- global mean pool ----------------
__global__ void pool_kernel(const float* __restrict__ x, const int* __restrict__ batch, int N) {
    int i = blockIdx.x * blockDim.x + threadIdx.x;
    if (i >= N * 64) return;
    int n = i >> 6, f = i & 63;
    int b = batch[n];
    atomicAdd(&g_pool[b * 64 + f], x[i]);
    if (f == 0) atomicAdd(&g_cnt[b], 1.0f);
}

// ---------------- MLP head: one block per graph ----------------
__global__ void mlp_kernel(const float* __restrict__ fw1, const float* __restrict__ fb1,
                           const float* __restrict__ fw2, const float* __restrict__ fb2,
                           const float* __restrict__ fw3, const float* __restrict__ fb3,
                           float* __restrict__ out)
{
    __shared__ float p[64], z1[128], z2[32];
    int gph = blockIdx.x;
    int t = threadIdx.x;   // 128 threads
    if (t < 64) p[t] = g_pool[gph * 64 + t] / fmaxf(g_cnt[gph], 1.0f);
    __syncthreads();
    float a = fb1[t];
    #pragma unroll 8
    for (int k = 0; k < 64; k++) a += p[k] * fw1[k * 128 + t];
    z1[t] = leaky02(a);
    __syncthreads();
    if (t < 32) {
        float b = fb2[t];
        #pragma unroll 8
        for (int k = 0; k < 128; k++) b += z1[k] * fw2[k * 32 + t];
        z2[t] = leaky02(b);
    }
    __syncthreads();
    if (t < 2) {
        float c = fb3[t];
        #pragma unroll
        for (int k = 0; k < 32; k++) c += z2[k] * fw3[k * 2 + t];
        out[gph * 2 + t] = c;
    }
}

// ---------------- host orchestration ----------------
static void run_gat_layer(const float* in, int Fin, const float* W,
                          const float* atts, const float* attd,
                          int Hh, int C, const float* g, const float* bt,
                          int N,
                          float* hbuf, float* obuf)
{
    int HC = Hh * C;
    dim3 gb(HC / 64, (N + 127) / 128);
    gemm_kernel<<<gb, 256>>>(in, W, hbuf, N, Fin, HC);

    int nw = N * Hh;   // warps
    score_kernel<<<(nw * 32 + 255) / 256, 256>>>(hbuf, atts, attd, N, Hh, C);

    if (C == 64)
        aggregate_kernel<64><<<(nw * 32 + 255) / 256, 256>>>(hbuf, obuf, N, Hh);
    else
        aggregate_kernel<32><<<(nw * 32 + 255) / 256, 256>>>(hbuf, obuf, N, Hh);

    bn_zero_kernel<<<1, HC>>>();
    bn_stats_kernel<<<256, HC>>>(obuf, N, HC);
    int nz = N * HC;
    bn_elu_kernel<<<(nz + 255) / 256, 256>>>(obuf, N, HC, g, bt);
}

extern "C" void kernel_launch(void* const* d_in, const int* in_sizes, int n_in,
                              void* d_out, int out_size)
{
    const float* x     = (const float*)d_in[0];
    const int*   ei    = (const int*)  d_in[1];
    const int*   batch = (const int*)  d_in[2];
    const float* W1  = (const float*)d_in[3];
    const float* as1 = (const float*)d_in[4];
    const float* ad1 = (const float*)d_in[5];
    const float* W2  = (const float*)d_in[7];
    const float* as2 = (const float*)d_in[8];
    const float* ad2 = (const float*)d_in[9];
    const float* W3  = (const float*)d_in[11];
    const float* as3 = (const float*)d_in[12];
    const float* ad3 = (const float*)d_in[13];
    const float* g1  = (const float*)d_in[15];
    const float* bt1 = (const float*)d_in[16];
    const float* g2  = (const float*)d_in[17];
    const float* bt2 = (const float*)d_in[18];
    const float* g3  = (const float*)d_in[19];
    const float* bt3 = (const float*)d_in[20];
    const float* fw1 = (const float*)d_in[21];
    const float* fb1 = (const float*)d_in[22];
    const float* fw2 = (const float*)d_in[23];
    const float* fb2 = (const float*)d_in[24];
    const float* fw3 = (const float*)d_in[25];
    const float* fb3 = (const float*)d_in[26];

    int N = in_sizes[0] / 128;
    int E = in_sizes[1] / 2;

    float *hbuf, *obuf;
    cudaGetSymbolAddress((void**)&hbuf, g_h);
    cudaGetSymbolAddress((void**)&obuf, g_out);

    // --- CSR build (once per call; reused by all 3 layers) ---
    init_once_kernel<<<(N + 255) / 256, 256>>>(N);
    count_kernel<<<(E + 255) / 256, 256>>>(ei, E);
    scan_kernel<<<1, 1024>>>(N);
    selfloop_kernel<<<(N + 255) / 256, 256>>>(N);
    scatter_kernel<<<(E + 255) / 256, 256>>>(ei, E);

    // biases b1/b2/b3 cancel inside the following BatchNorm (constant per-feature
    // shift removed by mean subtraction), so they are skipped.
    run_gat_layer(x,    128, W1, as1, ad1, 4, 64, g1, bt1, N, hbuf, obuf);
    run_gat_layer(obuf, 256, W2, as2, ad2, 4, 32, g2, bt2, N, hbuf, obuf);
    run_gat_layer(obuf, 128, W3, as3, ad3, 1, 64, g3, bt3, N, hbuf, obuf);

    pool_kernel<<<(N * 64 + 255) / 256, 256>>>(obuf, batch, N);
    mlp_kernel<<<64, 128>>>(fw1, fb1, fw2, fb2, fw3, fb3, (float*)d_out);
}

// round 9
// speedup vs baseline: 3.4911x; 1.1990x over previous
#include <cuda_runtime.h>
#include <math.h>

// ---------------- scratch (static device globals; no allocation) ----------------
__device__ float g_h  [50000 * 256];   // post-GEMM features for current layer
__device__ float g_out[50000 * 256];   // aggregated output / next-layer input
__device__ float g_as [50000 * 4];     // per-node src scores
__device__ float g_ad [50000 * 4];     // per-node dst scores
__device__ int   g_deg[50000];
__device__ int   g_off[50001];
__device__ int   g_cur[50000];
__device__ int   g_csr[850000];        // E + N entries (src ids, grouped by dst)
__device__ int   g_bsum[256];
__device__ float g_bnsum[256];
__device__ float g_bnsq [256];
__device__ float g_pool[64 * 64];
__device__ float g_cnt [64];

__device__ __forceinline__ float leaky02(float v) { return v > 0.f ? v : 0.2f * v; }

__device__ __forceinline__ unsigned f2tf32(float x) {
    unsigned r; asm("cvt.rna.tf32.f32 %0, %1;" : "=r"(r) : "f"(x)); return r;
}

__device__ __forceinline__ void mma_tf32(float* d, const unsigned* a, const unsigned* b) {
    asm volatile(
        "mma.sync.aligned.m16n8k8.row.col.f32.tf32.tf32.f32 "
        "{%0,%1,%2,%3}, {%4,%5,%6,%7}, {%8,%9}, {%0,%1,%2,%3};"
        : "+f"(d[0]), "+f"(d[1]), "+f"(d[2]), "+f"(d[3])
        : "r"(a[0]), "r"(a[1]), "r"(a[2]), "r"(a[3]), "r"(b[0]), "r"(b[1]));
}

// ---------------- one-time init ----------------
__global__ void init_once_kernel(int N) {
    int i = blockIdx.x * blockDim.x + threadIdx.x;
    if (i < N) g_deg[i] = 0;
    if (i < 64 * 64) g_pool[i] = 0.f;
    if (i < 64) g_cnt[i] = 0.f;
}

// ---------------- CSR build ----------------
__global__ void count_kernel(const int* __restrict__ ei, int E) {
    int e = blockIdx.x * blockDim.x + threadIdx.x;
    if (e < E) atomicAdd(&g_deg[ei[E + e]], 1);
}

// 3-stage parallel scan of (deg[i]+1) -> exclusive offsets in g_off
__global__ void partial_kernel(int N) {          // grid = nb, block = 256
    __shared__ int sh[256];
    int i = blockIdx.x * 256 + threadIdx.x;
    sh[threadIdx.x] = (i < N) ? (g_deg[i] + 1) : 0;
    __syncthreads();
    for (int o = 128; o; o >>= 1) {
        if (threadIdx.x < o) sh[threadIdx.x] += sh[threadIdx.x + o];
        __syncthreads();
    }
    if (threadIdx.x == 0) g_bsum[blockIdx.x] = sh[0];
}

__global__ void bscan_kernel(int nb) {           // 1 block, 256 thr: exclusive scan of g_bsum
    __shared__ int sh[256];
    int v = (threadIdx.x < nb) ? g_bsum[threadIdx.x] : 0;
    sh[threadIdx.x] = v;
    __syncthreads();
    for (int o = 1; o < 256; o <<= 1) {
        int t = (threadIdx.x >= o) ? sh[threadIdx.x - o] : 0;
        __syncthreads();
        sh[threadIdx.x] += t;
        __syncthreads();
    }
    if (threadIdx.x < nb) g_bsum[threadIdx.x] = sh[threadIdx.x] - v;
}

__global__ void off_kernel(int N) {              // grid = nb, block = 256
    __shared__ int sh[256];
    int i = blockIdx.x * 256 + threadIdx.x;
    int v = (i < N) ? (g_deg[i] + 1) : 0;
    sh[threadIdx.x] = v;
    __syncthreads();
    for (int o = 1; o < 256; o <<= 1) {
        int t = (threadIdx.x >= o) ? sh[threadIdx.x - o] : 0;
        __syncthreads();
        sh[threadIdx.x] += t;
        __syncthreads();
    }
    if (i < N) g_off[i + 1] = g_bsum[blockIdx.x] + sh[threadIdx.x];
    if (i == 0) g_off[0] = 0;
}

__global__ void selfloop_kernel(int N) {
    int n = blockIdx.x * blockDim.x + threadIdx.x;
    if (n < N) {
        g_csr[g_off[n]] = n;   // self loop first
        g_cur[n] = 0;
    }
}

__global__ void scatter_kernel(const int* __restrict__ ei, int E) {
    int e = blockIdx.x * blockDim.x + threadIdx.x;
    if (e >= E) return;
    int d = ei[E + e];
    int pos = g_off[d] + 1 + atomicAdd(&g_cur[d], 1);
    g_csr[pos] = ei[e];
}

// ---------------- TF32 tensor-core GEMM: C[N,K] = A[N,M] @ B[M,K] ----------------
// BM=128, BN=64, BK=32; 128 threads = 4 warps, warp tile 64x32 (4 m-atoms x 4 n-atoms, m16n8k8)
__global__ __launch_bounds__(128) void gemm_tc_kernel(
    const float* __restrict__ A, const float* __restrict__ B, float* __restrict__ C,
    int N, int M, int K)
{
    // A smem: logical [r][k], r<128, k<32; phys word = r*32 + (k ^ 4*(r&7))  (XOR swizzle)
    // B smem: [k][n], stride 72 (== 8 mod 32 -> conflict-free frags)
    __shared__ unsigned As[128 * 32];
    __shared__ unsigned Bs[32 * 72];

    int t = threadIdx.x;
    int lane = t & 31;
    int wid = t >> 5;
    int g = lane >> 2;           // 0..7
    int q = lane & 3;            // 0..3
    int warpM = (wid >> 1) * 64;
    int warpN = (wid & 1) * 32;
    int row0 = blockIdx.y * 128;
    int col0 = blockIdx.x * 64;

    float acc[4][4][4];
    #pragma unroll
    for (int i = 0; i < 4; i++)
        #pragma unroll
        for (int j = 0; j < 4; j++)
            #pragma unroll
            for (int r = 0; r < 4; r++) acc[i][j][r] = 0.f;

    for (int k0 = 0; k0 < M; k0 += 32) {
        // ---- load A tile: 128x32 floats = 1024 float4; idx: r = idx>>3, kq = idx&7
        #pragma unroll
        for (int s = 0; s < 8; s++) {
            int idx = t + s * 128;
            int r = idx >> 3;
            int k4 = (idx & 7) * 4;
            int gr = row0 + r;
            float4 v = make_float4(0.f, 0.f, 0.f, 0.f);
            if (gr < N) v = *(const float4*)&A[(size_t)gr * M + k0 + k4];
            int sw = (k4 ^ (4 * (r & 7)));
            unsigned* p = &As[r * 32 + sw];
            p[0] = f2tf32(v.x); p[1] = f2tf32(v.y); p[2] = f2tf32(v.z); p[3] = f2tf32(v.w);
        }
        // ---- load B tile: 32x64 floats = 512 float4; idx: k = idx>>4, n4 = (idx&15)*4
        #pragma unroll
        for (int s = 0; s < 4; s++) {
            int idx = t + s * 128;
            int k = idx >> 4;
            int n4 = (idx & 15) * 4;
            float4 v = *(const float4*)&B[(size_t)(k0 + k) * K + col0 + n4];
            unsigned* p = &Bs[k * 72 + n4];
            p[0] = f2tf32(v.x); p[1] = f2tf32(v.y); p[2] = f2tf32(v.z); p[3] = f2tf32(v.w);
        }
        __syncthreads();

        #pragma unroll
        for (int kk = 0; kk < 4; kk++) {
            int kb = kk * 8;
            unsigned a[4][4], b[4][2];
            #pragma unroll
            for (int ma = 0; ma < 4; ma++) {
                int r0 = warpM + ma * 16 + g;
                int r1 = r0 + 8;
                int swz = 4 * (r0 & 7);        // == 4*g for both r0 and r1
                a[ma][0] = As[r0 * 32 + ((kb + q)     ^ swz)];
                a[ma][1] = As[r1 * 32 + ((kb + q)     ^ swz)];
                a[ma][2] = As[r0 * 32 + ((kb + q + 4) ^ swz)];
                a[ma][3] = As[r1 * 32 + ((kb + q + 4) ^ swz)];
            }
            #pragma unroll
            for (int na = 0; na < 4; na++) {
                int c = warpN + na * 8 + g;
                b[na][0] = Bs[(kb + q)     * 72 + c];
                b[na][1] = Bs[(kb + q + 4) * 72 + c];
            }
            #pragma unroll
            for (int ma = 0; ma < 4; ma++)
                #pragma unroll
                for (int na = 0; na < 4; na++)
                    mma_tf32(acc[ma][na], a[ma], b[na]);
        }
        __syncthreads();
    }

    // ---- epilogue: c0,c1 -> row g, cols 2q,2q+1 ; c2,c3 -> row g+8
    #pragma unroll
    for (int ma = 0; ma < 4; ma++) {
        int r0 = row0 + warpM + ma * 16 + g;
        int r1 = r0 + 8;
        #pragma unroll
        for (int na = 0; na < 4; na++) {
            int c = col0 + warpN + na * 8 + 2 * q;
            if (r0 < N) {
                float2 v0 = make_float2(acc[ma][na][0], acc[ma][na][1]);
                *(float2*)&C[(size_t)r0 * K + c] = v0;
            }
            if (r1 < N) {
                float2 v1 = make_float2(acc[ma][na][2], acc[ma][na][3]);
                *(float2*)&C[(size_t)r1 * K + c] = v1;
            }
        }
    }
}

// ---------------- per-node attention scores: warp per (node, head) ----------------
__global__ void score_kernel(const float* __restrict__ h,
                             const float* __restrict__ atts, const float* __restrict__ attd,
                             int N, int Hh, int C)
{
    int w = (blockIdx.x * blockDim.x + threadIdx.x) >> 5;
    int lane = threadIdx.x & 31;
    if (w >= N * Hh) return;
    int n = w / Hh, hh = w - n * Hh;
    const float* row = h + (size_t)n * Hh * C + hh * C;
    float s = 0.f, d = 0.f;
    for (int c = lane; c < C; c += 32) {
        float v = row[c];
        s += v * atts[hh * C + c];
        d += v * attd[hh * C + c];
    }
    #pragma unroll
    for (int o = 16; o; o >>= 1) {
        s += __shfl_xor_sync(0xffffffffu, s, o);
        d += __shfl_xor_sync(0xffffffffu, d, o);
    }
    if (lane == 0) { g_as[w] = s; g_ad[w] = d; }
}

// ---------------- fused online-softmax aggregation: warp per (dst, head) ----------------
template <int C>
__global__ void aggregate_kernel(const float* __restrict__ h, float* __restrict__ out,
                                 int N, int Hh)
{
    int w = (blockIdx.x * blockDim.x + threadIdx.x) >> 5;
    int lane = threadIdx.x & 31;
    if (w >= N * Hh) return;
    int dst = w / Hh, hh = w - dst * Hh;
    int beg = g_off[dst], end = g_off[dst + 1];
    float ad = g_ad[w];
    constexpr int V = C / 32;
    float acc[V];
    #pragma unroll
    for (int v = 0; v < V; v++) acc[v] = 0.f;
    float m = -INFINITY, den = 0.f;

    for (int i = beg; i < end; i++) {
        int src = g_csr[i];
        float e = leaky02(g_as[src * Hh + hh] + ad);
        float mn = fmaxf(m, e);
        float scale = __expf(m - mn);     // 0 on first iteration (m=-inf)
        float wgt = __expf(e - mn);
        den = den * scale + wgt;
        const float* hp = h + (size_t)src * (Hh * C) + hh * C + lane;
        #pragma unroll
        for (int v = 0; v < V; v++)
            acc[v] = acc[v] * scale + wgt * hp[v * 32];
        m = mn;
    }
    float inv = 1.f / (den + 1e-16f);
    float* op = out + (size_t)dst * (Hh * C) + hh * C + lane;
    #pragma unroll
    for (int v = 0; v < V; v++) op[v * 32] = acc[v] * inv;
}

// ---------------- batch norm ----------------
__global__ void bn_zero_kernel() {
    int i = threadIdx.x;
    g_bnsum[i] = 0.f;
    g_bnsq[i] = 0.f;
}

__global__ void bn_stats_kernel(const float* __restrict__ x, int N, int F) {
    int f = threadIdx.x;   // blockDim.x == F
    float s = 0.f, q = 0.f;
    for (int n = blockIdx.x; n < N; n += gridDim.x) {
        float v = x[(size_t)n * F + f];
        s += v; q += v * v;
    }
    atomicAdd(&g_bnsum[f], s);
    atomicAdd(&g_bnsq[f], q);
}

__global__ void bn_elu_kernel(float* __restrict__ x, int N, int F,
                              const float* __restrict__ g, const float* __restrict__ bt)
{
    int i = blockIdx.x * blockDim.x + threadIdx.x;
    if (i >= N * F) return;
    int f = i % F;
    float inv_n = 1.0f / (float)N;
    float mu = g_bnsum[f] * inv_n;
    float var = g_bnsq[f] * inv_n - mu * mu;
    float v = (x[i] - mu) * rsqrtf(var + 1e-5f) * g[f] + bt[f];
    x[i] = v > 0.f ? v : (expf(v) - 1.f);
}

// ---------------- global mean pool ----------------
__global__ void pool_kernel(const float* __restrict__ x, const int* __restrict__ batch, int N) {
    int i = blockIdx.x * blockDim.x + threadIdx.x;
    if (i >= N * 64) return;
    int n = i >> 6, f = i & 63;
    int b = batch[n];
    atomicAdd(&g_pool[b * 64 + f], x[i]);
    if (f == 0) atomicAdd(&g_cnt[b], 1.0f);
}

// ---------------- MLP head: one block per graph ----------------
__global__ void mlp_kernel(const float* __restrict__ fw1, const float* __restrict__ fb1,
                           const float* __restrict__ fw2, const float* __restrict__ fb2,
                           const float* __restrict__ fw3, const float* __restrict__ fb3,
                           float* __restrict__ out)
{
    __shared__ float p[64], z1[128], z2[32];
    int gph = blockIdx.x;
    int t = threadIdx.x;   // 128 threads
    if (t < 64) p[t] = g_pool[gph * 64 + t] / fmaxf(g_cnt[gph], 1.0f);
    __syncthreads();
    float a = fb1[t];
    #pragma unroll 8
    for (int k = 0; k < 64; k++) a += p[k] * fw1[k * 128 + t];
    z1[t] = leaky02(a);
    __syncthreads();
    if (t < 32) {
        float b = fb2[t];
        #pragma unroll 8
        for (int k = 0; k < 128; k++) b += z1[k] * fw2[k * 32 + t];
        z2[t] = leaky02(b);
    }
    __syncthreads();
    if (t < 2) {
        float c = fb3[t];
        #pragma unroll
        for (int k = 0; k < 32; k++) c += z2[k] * fw3[k * 2 + t];
        out[gph * 2 + t] = c;
    }
}

// ---------------- host orchestration ----------------
static void run_gat_layer(const float* in, int Fin, const float* W,
                          const float* atts, const float* attd,
                          int Hh, int C, const float* g, const float* bt,
                          int N,
                          float* hbuf, float* obuf)
{
    int HC = Hh * C;
    dim3 gb(HC / 64, (N + 127) / 128);
    gemm_tc_kernel<<<gb, 128>>>(in, W, hbuf, N, Fin, HC);

    int nw = N * Hh;   // warps
    score_kernel<<<(nw * 32 + 255) / 256, 256>>>(hbuf, atts, attd, N, Hh, C);

    if (C == 64)
        aggregate_kernel<64><<<(nw * 32 + 255) / 256, 256>>>(hbuf, obuf, N, Hh);
    else
        aggregate_kernel<32><<<(nw * 32 + 255) / 256, 256>>>(hbuf, obuf, N, Hh);

    bn_zero_kernel<<<1, HC>>>();
    bn_stats_kernel<<<256, HC>>>(obuf, N, HC);
    int nz = N * HC;
    bn_elu_kernel<<<(nz + 255) / 256, 256>>>(obuf, N, HC, g, bt);
}

extern "C" void kernel_launch(void* const* d_in, const int* in_sizes, int n_in,
                              void* d_out, int out_size)
{
    const float* x     = (const float*)d_in[0];
    const int*   ei    = (const int*)  d_in[1];
    const int*   batch = (const int*)  d_in[2];
    const float* W1  = (const float*)d_in[3];
    const float* as1 = (const float*)d_in[4];
    const float* ad1 = (const float*)d_in[5];
    const float* W2  = (const float*)d_in[7];
    const float* as2 = (const float*)d_in[8];
    const float* ad2 = (const float*)d_in[9];
    const float* W3  = (const float*)d_in[11];
    const float* as3 = (const float*)d_in[12];
    const float* ad3 = (const float*)d_in[13];
    const float* g1  = (const float*)d_in[15];
    const float* bt1 = (const float*)d_in[16];
    const float* g2  = (const float*)d_in[17];
    const float* bt2 = (const float*)d_in[18];
    const float* g3  = (const float*)d_in[19];
    const float* bt3 = (const float*)d_in[20];
    const float* fw1 = (const float*)d_in[21];
    const float* fb1 = (const float*)d_in[22];
    const float* fw2 = (const float*)d_in[23];
    const float* fb2 = (const float*)d_in[24];
    const float* fw3 = (const float*)d_in[25];
    const float* fb3 = (const float*)d_in[26];

    int N = in_sizes[0] / 128;
    int E = in_sizes[1] / 2;
    int nb = (N + 255) / 256;   // 196 <= 256

    float *hbuf, *obuf;
    cudaGetSymbolAddress((void**)&hbuf, g_h);
    cudaGetSymbolAddress((void**)&obuf, g_out);

    // --- CSR build (once per call; reused by all 3 layers) ---
    init_once_kernel<<<(N + 255) / 256, 256>>>(N);
    count_kernel<<<(E + 255) / 256, 256>>>(ei, E);
    partial_kernel<<<nb, 256>>>(N);
    bscan_kernel<<<1, 256>>>(nb);
    off_kernel<<<nb, 256>>>(N);
    selfloop_kernel<<<(N + 255) / 256, 256>>>(N);
    scatter_kernel<<<(E + 255) / 256, 256>>>(ei, E);

    // biases b1/b2/b3 cancel inside the following BatchNorm (constant per-feature
    // shift removed by mean subtraction), so they are skipped.
    run_gat_layer(x,    128, W1, as1, ad1, 4, 64, g1, bt1, N, hbuf, obuf);
    run_gat_layer(obuf, 256, W2, as2, ad2, 4, 32, g2, bt2, N, hbuf, obuf);
    run_gat_layer(obuf, 128, W3, as3, ad3, 1, 64, g3, bt3, N, hbuf, obuf);

    pool_kernel<<<(N * 64 + 255) / 256, 256>>>(obuf, batch, N);
    mlp_kernel<<<64, 128>>>(fw1, fb1, fw2, fb2, fw3, fb3, (float*)d_out);
}

// round 10
// speedup vs baseline: 3.7406x; 1.0715x over previous
#include <cuda_runtime.h>
#include <math.h>

// ---------------- scratch (static device globals; no allocation) ----------------
__device__ float g_h  [50000 * 256];   // post-GEMM features for current layer
__device__ float g_out[50000 * 256];   // aggregated output / next-layer input
__device__ float g_as [50000 * 4];     // per-node src scores
__device__ float g_ad [50000 * 4];     // per-node dst scores
__device__ int   g_deg[50000];
__device__ int   g_off[50001];
__device__ int   g_cur[50000];
__device__ int   g_csr[850000];        // E + N entries (src ids, grouped by dst)
__device__ int   g_bsum[256];
__device__ float g_bnsum[256];
__device__ float g_bnsq [256];
__device__ float g_pool[64 * 64];
__device__ float g_cnt [64];

__device__ __forceinline__ float leaky02(float v) { return v > 0.f ? v : 0.2f * v; }

__device__ __forceinline__ unsigned f2tf32(float x) {
    unsigned r; asm("cvt.rna.tf32.f32 %0, %1;" : "=r"(r) : "f"(x)); return r;
}

__device__ __forceinline__ void mma_tf32(float* d, const unsigned* a, const unsigned* b) {
    asm volatile(
        "mma.sync.aligned.m16n8k8.row.col.f32.tf32.tf32.f32 "
        "{%0,%1,%2,%3}, {%4,%5,%6,%7}, {%8,%9}, {%0,%1,%2,%3};"
        : "+f"(d[0]), "+f"(d[1]), "+f"(d[2]), "+f"(d[3])
        : "r"(a[0]), "r"(a[1]), "r"(a[2]), "r"(a[3]), "r"(b[0]), "r"(b[1]));
}

// ---------------- one-time init ----------------
__global__ void init_once_kernel(int N) {
    int i = blockIdx.x * blockDim.x + threadIdx.x;
    if (i < N) g_deg[i] = 0;
    if (i < 64 * 64) g_pool[i] = 0.f;
    if (i < 64) g_cnt[i] = 0.f;
}

// ---------------- CSR build ----------------
__global__ void count_kernel(const int* __restrict__ ei, int E) {
    int e = blockIdx.x * blockDim.x + threadIdx.x;
    if (e < E) atomicAdd(&g_deg[ei[E + e]], 1);
}

// 3-stage parallel scan of (deg[i]+1) -> exclusive offsets in g_off
__global__ void partial_kernel(int N) {          // grid = nb, block = 256
    __shared__ int sh[256];
    int i = blockIdx.x * 256 + threadIdx.x;
    sh[threadIdx.x] = (i < N) ? (g_deg[i] + 1) : 0;
    __syncthreads();
    for (int o = 128; o; o >>= 1) {
        if (threadIdx.x < o) sh[threadIdx.x] += sh[threadIdx.x + o];
        __syncthreads();
    }
    if (threadIdx.x == 0) g_bsum[blockIdx.x] = sh[0];
}

__global__ void bscan_kernel(int nb) {           // 1 block, 256 thr: exclusive scan of g_bsum
    __shared__ int sh[256];
    int v = (threadIdx.x < nb) ? g_bsum[threadIdx.x] : 0;
    sh[threadIdx.x] = v;
    __syncthreads();
    for (int o = 1; o < 256; o <<= 1) {
        int t = (threadIdx.x >= o) ? sh[threadIdx.x - o] : 0;
        __syncthreads();
        sh[threadIdx.x] += t;
        __syncthreads();
    }
    if (threadIdx.x < nb) g_bsum[threadIdx.x] = sh[threadIdx.x] - v;
}

__global__ void off_kernel(int N) {              // grid = nb, block = 256
    __shared__ int sh[256];
    int i = blockIdx.x * 256 + threadIdx.x;
    int v = (i < N) ? (g_deg[i] + 1) : 0;
    sh[threadIdx.x] = v;
    __syncthreads();
    for (int o = 1; o < 256; o <<= 1) {
        int t = (threadIdx.x >= o) ? sh[threadIdx.x - o] : 0;
        __syncthreads();
        sh[threadIdx.x] += t;
        __syncthreads();
    }
    if (i < N) g_off[i + 1] = g_bsum[blockIdx.x] + sh[threadIdx.x];
    if (i == 0) g_off[0] = 0;
}

__global__ void selfloop_kernel(int N) {
    int n = blockIdx.x * blockDim.x + threadIdx.x;
    if (n < N) {
        g_csr[g_off[n]] = n;   // self loop first
        g_cur[n] = 0;
    }
}

__global__ void scatter_kernel(const int* __restrict__ ei, int E) {
    int e = blockIdx.x * blockDim.x + threadIdx.x;
    if (e >= E) return;
    int d = ei[E + e];
    int pos = g_off[d] + 1 + atomicAdd(&g_cur[d], 1);
    g_csr[pos] = ei[e];
}

// ---------------- TF32 tensor-core GEMM: C[N,K] = A[N,M] @ B[M,K] ----------------
// BM=128, BN=64, BK=32; 128 threads = 4 warps, warp tile 64x32 (4 m-atoms x 4 n-atoms, m16n8k8)
__global__ __launch_bounds__(128) void gemm_tc_kernel(
    const float* __restrict__ A, const float* __restrict__ B, float* __restrict__ C,
    int N, int M, int K)
{
    // A smem: logical [r][k], r<128, k<32; phys word = r*32 + (k ^ 4*(r&7))  (XOR swizzle)
    // B smem: [k][n], stride 72 (== 8 mod 32 -> conflict-free frags)
    __shared__ unsigned As[128 * 32];
    __shared__ unsigned Bs[32 * 72];

    int t = threadIdx.x;
    int lane = t & 31;
    int wid = t >> 5;
    int g = lane >> 2;           // 0..7
    int q = lane & 3;            // 0..3
    int warpM = (wid >> 1) * 64;
    int warpN = (wid & 1) * 32;
    int row0 = blockIdx.y * 128;
    int col0 = blockIdx.x * 64;

    float acc[4][4][4];
    #pragma unroll
    for (int i = 0; i < 4; i++)
        #pragma unroll
        for (int j = 0; j < 4; j++)
            #pragma unroll
            for (int r = 0; r < 4; r++) acc[i][j][r] = 0.f;

    for (int k0 = 0; k0 < M; k0 += 32) {
        // ---- load A tile: 128x32 floats = 1024 float4; idx: r = idx>>3, kq = idx&7
        #pragma unroll
        for (int s = 0; s < 8; s++) {
            int idx = t + s * 128;
            int r = idx >> 3;
            int k4 = (idx & 7) * 4;
            int gr = row0 + r;
            float4 v = make_float4(0.f, 0.f, 0.f, 0.f);
            if (gr < N) v = *(const float4*)&A[(size_t)gr * M + k0 + k4];
            int sw = (k4 ^ (4 * (r & 7)));
            unsigned* p = &As[r * 32 + sw];
            p[0] = f2tf32(v.x); p[1] = f2tf32(v.y); p[2] = f2tf32(v.z); p[3] = f2tf32(v.w);
        }
        // ---- load B tile: 32x64 floats = 512 float4; idx: k = idx>>4, n4 = (idx&15)*4
        #pragma unroll
        for (int s = 0; s < 4; s++) {
            int idx = t + s * 128;
            int k = idx >> 4;
            int n4 = (idx & 15) * 4;
            float4 v = *(const float4*)&B[(size_t)(k0 + k) * K + col0 + n4];
            unsigned* p = &Bs[k * 72 + n4];
            p[0] = f2tf32(v.x); p[1] = f2tf32(v.y); p[2] = f2tf32(v.z); p[3] = f2tf32(v.w);
        }
        __syncthreads();

        #pragma unroll
        for (int kk = 0; kk < 4; kk++) {
            int kb = kk * 8;
            unsigned a[4][4], b[4][2];
            #pragma unroll
            for (int ma = 0; ma < 4; ma++) {
                int r0 = warpM + ma * 16 + g;
                int r1 = r0 + 8;
                int swz = 4 * (r0 & 7);        // == 4*g for both r0 and r1
                a[ma][0] = As[r0 * 32 + ((kb + q)     ^ swz)];
                a[ma][1] = As[r1 * 32 + ((kb + q)     ^ swz)];
                a[ma][2] = As[r0 * 32 + ((kb + q + 4) ^ swz)];
                a[ma][3] = As[r1 * 32 + ((kb + q + 4) ^ swz)];
            }
            #pragma unroll
            for (int na = 0; na < 4; na++) {
                int c = warpN + na * 8 + g;
                b[na][0] = Bs[(kb + q)     * 72 + c];
                b[na][1] = Bs[(kb + q + 4) * 72 + c];
            }
            #pragma unroll
            for (int ma = 0; ma < 4; ma++)
                #pragma unroll
                for (int na = 0; na < 4; na++)
                    mma_tf32(acc[ma][na], a[ma], b[na]);
        }
        __syncthreads();
    }

    // ---- epilogue: c0,c1 -> row g, cols 2q,2q+1 ; c2,c3 -> row g+8
    #pragma unroll
    for (int ma = 0; ma < 4; ma++) {
        int r0 = row0 + warpM + ma * 16 + g;
        int r1 = r0 + 8;
        #pragma unroll
        for (int na = 0; na < 4; na++) {
            int c = col0 + warpN + na * 8 + 2 * q;
            if (r0 < N) {
                float2 v0 = make_float2(acc[ma][na][0], acc[ma][na][1]);
                *(float2*)&C[(size_t)r0 * K + c] = v0;
            }
            if (r1 < N) {
                float2 v1 = make_float2(acc[ma][na][2], acc[ma][na][3]);
                *(float2*)&C[(size_t)r1 * K + c] = v1;
            }
        }
    }
}

// ---------------- per-node attention scores: warp per (node, head) ----------------
__global__ void score_kernel(const float* __restrict__ h,
                             const float* __restrict__ atts, const float* __restrict__ attd,
                             int N, int Hh, int C)
{
    int w = (blockIdx.x * blockDim.x + threadIdx.x) >> 5;
    int lane = threadIdx.x & 31;
    if (w >= N * Hh) return;
    int n = w / Hh, hh = w - n * Hh;
    const float* row = h + (size_t)n * Hh * C + hh * C;
    float s = 0.f, d = 0.f;
    for (int c = lane; c < C; c += 32) {
        float v = row[c];
        s += v * atts[hh * C + c];
        d += v * attd[hh * C + c];
    }
    #pragma unroll
    for (int o = 16; o; o >>= 1) {
        s += __shfl_xor_sync(0xffffffffu, s, o);
        d += __shfl_xor_sync(0xffffffffu, d, o);
    }
    if (lane == 0) { g_as[w] = s; g_ad[w] = d; }
}

// ---------------- fused softmax aggregation: warp per (dst, head), chunked-parallel ----------------
// Each 32-neighbor chunk: lanes load csr+score in parallel, warp-reduce max & sum(exp),
// then the weighted gather gets src/weight via shfl -> all h-row loads independent.
template <int C>
__global__ void aggregate_kernel(const float* __restrict__ h, float* __restrict__ out,
                                 int N, int Hh)
{
    int w = (blockIdx.x * blockDim.x + threadIdx.x) >> 5;
    int lane = threadIdx.x & 31;
    if (w >= N * Hh) return;
    int dst = w / Hh, hh = w - dst * Hh;
    int beg = g_off[dst], end = g_off[dst + 1];
    float ad = g_ad[w];
    constexpr int V = C / 32;
    float acc[V];
    #pragma unroll
    for (int v = 0; v < V; v++) acc[v] = 0.f;
    float m = -INFINITY, den = 0.f;

    for (int chunk = beg; chunk < end; chunk += 32) {
        int idx = chunk + lane;
        bool valid = idx < end;
        int src = valid ? g_csr[idx] : 0;
        float e = valid ? leaky02(g_as[src * Hh + hh] + ad) : -INFINITY;
        // warp max of this chunk
        float cm = e;
        #pragma unroll
        for (int o = 16; o; o >>= 1) cm = fmaxf(cm, __shfl_xor_sync(0xffffffffu, cm, o));
        float mn = fmaxf(m, cm);
        float scale = __expf(m - mn);   // 0 on first chunk (m = -inf)
        den *= scale;
        #pragma unroll
        for (int v = 0; v < V; v++) acc[v] *= scale;
        float ex = valid ? __expf(e - mn) : 0.f;
        float cs = ex;
        #pragma unroll
        for (int o = 16; o; o >>= 1) cs += __shfl_xor_sync(0xffffffffu, cs, o);
        den += cs;

        int cnt = min(32, end - chunk);
        int i = 0;
        for (; i + 4 <= cnt; i += 4) {
            int   s0 = __shfl_sync(0xffffffffu, src, i + 0);
            int   s1 = __shfl_sync(0xffffffffu, src, i + 1);
            int   s2 = __shfl_sync(0xffffffffu, src, i + 2);
            int   s3 = __shfl_sync(0xffffffffu, src, i + 3);
            float w0 = __shfl_sync(0xffffffffu, ex,  i + 0);
            float w1 = __shfl_sync(0xffffffffu, ex,  i + 1);
            float w2 = __shfl_sync(0xffffffffu, ex,  i + 2);
            float w3 = __shfl_sync(0xffffffffu, ex,  i + 3);
            const float* p0 = h + (size_t)s0 * (Hh * C) + hh * C + lane;
            const float* p1 = h + (size_t)s1 * (Hh * C) + hh * C + lane;
            const float* p2 = h + (size_t)s2 * (Hh * C) + hh * C + lane;
            const float* p3 = h + (size_t)s3 * (Hh * C) + hh * C + lane;
            #pragma unroll
            for (int v = 0; v < V; v++) {
                float f0 = p0[v * 32], f1 = p1[v * 32], f2 = p2[v * 32], f3 = p3[v * 32];
                acc[v] += w0 * f0;
                acc[v] += w1 * f1;
                acc[v] += w2 * f2;
                acc[v] += w3 * f3;
            }
        }
        for (; i < cnt; i++) {
            int   s0 = __shfl_sync(0xffffffffu, src, i);
            float w0 = __shfl_sync(0xffffffffu, ex,  i);
            const float* p0 = h + (size_t)s0 * (Hh * C) + hh * C + lane;
            #pragma unroll
            for (int v = 0; v < V; v++) acc[v] += w0 * p0[v * 32];
        }
        m = mn;
    }
    float inv = 1.f / (den + 1e-16f);
    float* op = out + (size_t)dst * (Hh * C) + hh * C + lane;
    #pragma unroll
    for (int v = 0; v < V; v++) op[v * 32] = acc[v] * inv;
}

// ---------------- batch norm ----------------
__global__ void bn_zero_kernel() {
    int i = threadIdx.x;
    g_bnsum[i] = 0.f;
    g_bnsq[i] = 0.f;
}

__global__ void bn_stats_kernel(const float* __restrict__ x, int N, int F) {
    int f = threadIdx.x;   // blockDim.x == F
    float s = 0.f, q = 0.f;
    for (int n = blockIdx.x; n < N; n += gridDim.x) {
        float v = x[(size_t)n * F + f];
        s += v; q += v * v;
    }
    atomicAdd(&g_bnsum[f], s);
    atomicAdd(&g_bnsq[f], q);
}

__global__ void bn_elu_kernel(float* __restrict__ x, int N, int F,
                              const float* __restrict__ g, const float* __restrict__ bt)
{
    int i = blockIdx.x * blockDim.x + threadIdx.x;
    if (i >= N * F) return;
    int f = i % F;
    float inv_n = 1.0f / (float)N;
    float mu = g_bnsum[f] * inv_n;
    float var = g_bnsq[f] * inv_n - mu * mu;
    float v = (x[i] - mu) * rsqrtf(var + 1e-5f) * g[f] + bt[f];
    x[i] = v > 0.f ? v : (expf(v) - 1.f);
}

// ---------------- global mean pool ----------------
__global__ void pool_kernel(const float* __restrict__ x, const int* __restrict__ batch, int N) {
    int i = blockIdx.x * blockDim.x + threadIdx.x;
    if (i >= N * 64) return;
    int n = i >> 6, f = i & 63;
    int b = batch[n];
    atomicAdd(&g_pool[b * 64 + f], x[i]);
    if (f == 0) atomicAdd(&g_cnt[b], 1.0f);
}

// ---------------- MLP head: one block per graph ----------------
__global__ void mlp_kernel(const float* __restrict__ fw1, const float* __restrict__ fb1,
                           const float* __restrict__ fw2, const float* __restrict__ fb2,
                           const float* __restrict__ fw3, const float* __restrict__ fb3,
                           float* __restrict__ out)
{
    __shared__ float p[64], z1[128], z2[32];
    int gph = blockIdx.x;
    int t = threadIdx.x;   // 128 threads
    if (t < 64) p[t] = g_pool[gph * 64 + t] / fmaxf(g_cnt[gph], 1.0f);
    __syncthreads();
    float a = fb1[t];
    #pragma unroll 8
    for (int k = 0; k < 64; k++) a += p[k] * fw1[k * 128 + t];
    z1[t] = leaky02(a);
    __syncthreads();
    if (t < 32) {
        float b = fb2[t];
        #pragma unroll 8
        for (int k = 0; k < 128; k++) b += z1[k] * fw2[k * 32 + t];
        z2[t] = leaky02(b);
    }
    __syncthreads();
    if (t < 2) {
        float c = fb3[t];
        #pragma unroll
        for (int k = 0; k < 32; k++) c += z2[k] * fw3[k * 2 + t];
        out[gph * 2 + t] = c;
    }
}

// ---------------- host orchestration ----------------
static void run_gat_layer(const float* in, int Fin, const float* W,
                          const float* atts, const float* attd,
                          int Hh, int C, const float* g, const float* bt,
                          int N,
                          float* hbuf, float* obuf)
{
    int HC = Hh * C;
    dim3 gb(HC / 64, (N + 127) / 128);
    gemm_tc_kernel<<<gb, 128>>>(in, W, hbuf, N, Fin, HC);

    int nw = N * Hh;   // warps
    score_kernel<<<(nw * 32 + 255) / 256, 256>>>(hbuf, atts, attd, N, Hh, C);

    if (C == 64)
        aggregate_kernel<64><<<(nw * 32 + 255) / 256, 256>>>(hbuf, obuf, N, Hh);
    else
        aggregate_kernel<32><<<(nw * 32 + 255) / 256, 256>>>(hbuf, obuf, N, Hh);

    bn_zero_kernel<<<1, HC>>>();
    bn_stats_kernel<<<256, HC>>>(obuf, N, HC);
    int nz = N * HC;
    bn_elu_kernel<<<(nz + 255) / 256, 256>>>(obuf, N, HC, g, bt);
}

extern "C" void kernel_launch(void* const* d_in, const int* in_sizes, int n_in,
                              void* d_out, int out_size)
{
    const float* x     = (const float*)d_in[0];
    const int*   ei    = (const int*)  d_in[1];
    const int*   batch = (const int*)  d_in[2];
    const float* W1  = (const float*)d_in[3];
    const float* as1 = (const float*)d_in[4];
    const float* ad1 = (const float*)d_in[5];
    const float* W2  = (const float*)d_in[7];
    const float* as2 = (const float*)d_in[8];
    const float* ad2 = (const float*)d_in[9];
    const float* W3  = (const float*)d_in[11];
    const float* as3 = (const float*)d_in[12];
    const float* ad3 = (const float*)d_in[13];
    const float* g1  = (const float*)d_in[15];
    const float* bt1 = (const float*)d_in[16];
    const float* g2  = (const float*)d_in[17];
    const float* bt2 = (const float*)d_in[18];
    const float* g3  = (const float*)d_in[19];
    const float* bt3 = (const float*)d_in[20];
    const float* fw1 = (const float*)d_in[21];
    const float* fb1 = (const float*)d_in[22];
    const float* fw2 = (const float*)d_in[23];
    const float* fb2 = (const float*)d_in[24];
    const float* fw3 = (const float*)d_in[25];
    const float* fb3 = (const float*)d_in[26];

    int N = in_sizes[0] / 128;
    int E = in_sizes[1] / 2;
    int nb = (N + 255) / 256;   // 196 <= 256

    float *hbuf, *obuf;
    cudaGetSymbolAddress((void**)&hbuf, g_h);
    cudaGetSymbolAddress((void**)&obuf, g_out);

    // --- CSR build (once per call; reused by all 3 layers) ---
    init_once_kernel<<<(N + 255) / 256, 256>>>(N);
    count_kernel<<<(E + 255) / 256, 256>>>(ei, E);
    partial_kernel<<<nb, 256>>>(N);
    bscan_kernel<<<1, 256>>>(nb);
    off_kernel<<<nb, 256>>>(N);
    selfloop_kernel<<<(N + 255) / 256, 256>>>(N);
    scatter_kernel<<<(E + 255) / 256, 256>>>(ei, E);

    // biases b1/b2/b3 cancel inside the following BatchNorm (constant per-feature
    // shift removed by mean subtraction), so they are skipped.
    run_gat_layer(x,    128, W1, as1, ad1, 4, 64, g1, bt1, N, hbuf, obuf);
    run_gat_layer(obuf, 256, W2, as2, ad2, 4, 32, g2, bt2, N, hbuf, obuf);
    run_gat_layer(obuf, 128, W3, as3, ad3, 1, 64, g3, bt3, N, hbuf, obuf);

    pool_kernel<<<(N * 64 + 255) / 256, 256>>>(obuf, batch, N);
    mlp_kernel<<<64, 128>>>(fw1, fb1, fw2, fb2, fw3, fb3, (float*)d_out);
}

// round 11
// speedup vs baseline: 3.9012x; 1.0429x over previous
#include <cuda_runtime.h>
#include <math.h>

// ---------------- scratch (static device globals; no allocation) ----------------
__device__ float g_h  [50000 * 256];   // post-GEMM features for current layer
__device__ float g_out[50000 * 256];   // aggregated output / next-layer input
__device__ float g_as [50000 * 4];     // per-node src scores
__device__ float g_ad [50000 * 4];     // per-node dst scores
__device__ int   g_deg[50000];
__device__ int   g_off[50001];
__device__ int   g_cur[50000];
__device__ int   g_csr[850000];        // E + N entries (src ids, grouped by dst)
__device__ int   g_bsum[256];
__device__ float g_bnsum[256];
__device__ float g_bnsq [256];
__device__ float g_pool[64 * 64];
__device__ float g_cnt [64];

__device__ __forceinline__ float leaky02(float v) { return v > 0.f ? v : 0.2f * v; }

__device__ __forceinline__ unsigned f2tf32(float x) {
    unsigned r; asm("cvt.rna.tf32.f32 %0, %1;" : "=r"(r) : "f"(x)); return r;
}

__device__ __forceinline__ void mma_tf32(float* d, const unsigned* a, const unsigned* b) {
    asm volatile(
        "mma.sync.aligned.m16n8k8.row.col.f32.tf32.tf32.f32 "
        "{%0,%1,%2,%3}, {%4,%5,%6,%7}, {%8,%9}, {%0,%1,%2,%3};"
        : "+f"(d[0]), "+f"(d[1]), "+f"(d[2]), "+f"(d[3])
        : "r"(a[0]), "r"(a[1]), "r"(a[2]), "r"(a[3]), "r"(b[0]), "r"(b[1]));
}

// ---------------- one-time init ----------------
__global__ void init_once_kernel(int N) {
    int i = blockIdx.x * blockDim.x + threadIdx.x;
    if (i < N) g_deg[i] = 0;
    if (i < 64 * 64) g_pool[i] = 0.f;
    if (i < 64) g_cnt[i] = 0.f;
}

// per-layer init: zero score accumulators + bn accumulators
__global__ void layer_init_kernel(int nm) {
    int i = blockIdx.x * blockDim.x + threadIdx.x;
    if (i < nm) { g_as[i] = 0.f; g_ad[i] = 0.f; }
    if (i < 256) { g_bnsum[i] = 0.f; g_bnsq[i] = 0.f; }
}

// ---------------- CSR build ----------------
__global__ void count_kernel(const int* __restrict__ ei, int E) {
    int e = blockIdx.x * blockDim.x + threadIdx.x;
    if (e < E) atomicAdd(&g_deg[ei[E + e]], 1);
}

// 3-stage parallel scan of (deg[i]+1) -> exclusive offsets in g_off
__global__ void partial_kernel(int N) {          // grid = nb, block = 256
    __shared__ int sh[256];
    int i = blockIdx.x * 256 + threadIdx.x;
    sh[threadIdx.x] = (i < N) ? (g_deg[i] + 1) : 0;
    __syncthreads();
    for (int o = 128; o; o >>= 1) {
        if (threadIdx.x < o) sh[threadIdx.x] += sh[threadIdx.x + o];
        __syncthreads();
    }
    if (threadIdx.x == 0) g_bsum[blockIdx.x] = sh[0];
}

__global__ void bscan_kernel(int nb) {           // 1 block, 256 thr: exclusive scan of g_bsum
    __shared__ int sh[256];
    int v = (threadIdx.x < nb) ? g_bsum[threadIdx.x] : 0;
    sh[threadIdx.x] = v;
    __syncthreads();
    for (int o = 1; o < 256; o <<= 1) {
        int t = (threadIdx.x >= o) ? sh[threadIdx.x - o] : 0;
        __syncthreads();
        sh[threadIdx.x] += t;
        __syncthreads();
    }
    if (threadIdx.x < nb) g_bsum[threadIdx.x] = sh[threadIdx.x] - v;
}

__global__ void off_kernel(int N) {              // grid = nb, block = 256
    __shared__ int sh[256];
    int i = blockIdx.x * 256 + threadIdx.x;
    int v = (i < N) ? (g_deg[i] + 1) : 0;
    sh[threadIdx.x] = v;
    __syncthreads();
    for (int o = 1; o < 256; o <<= 1) {
        int t = (threadIdx.x >= o) ? sh[threadIdx.x - o] : 0;
        __syncthreads();
        sh[threadIdx.x] += t;
        __syncthreads();
    }
    if (i < N) g_off[i + 1] = g_bsum[blockIdx.x] + sh[threadIdx.x];
    if (i == 0) g_off[0] = 0;
}

__global__ void selfloop_kernel(int N) {
    int n = blockIdx.x * blockDim.x + threadIdx.x;
    if (n < N) {
        g_csr[g_off[n]] = n;   // self loop first
        g_cur[n] = 0;
    }
}

__global__ void scatter_kernel(const int* __restrict__ ei, int E) {
    int e = blockIdx.x * blockDim.x + threadIdx.x;
    if (e >= E) return;
    int d = ei[E + e];
    int pos = g_off[d] + 1 + atomicAdd(&g_cur[d], 1);
    g_csr[pos] = ei[e];
}

// ---------------- TF32 tensor-core GEMM with fused attention-score epilogue ----------------
// C[N,K] = A[N,M] @ B[M,K]; BM=128, BN=64, BK=32; 128 threads = 4 warps, warp tile 64x32.
// Epilogue also accumulates s[r,head] = sum_c h[r,c]*atts[head,c] (and attd) via atomics.
// Each warp's 32 output columns lie inside a single head (Chead in {32,64}).
__global__ __launch_bounds__(128) void gemm_tc_kernel(
    const float* __restrict__ A, const float* __restrict__ B, float* __restrict__ C,
    int N, int M, int K,
    const float* __restrict__ atts, const float* __restrict__ attd, int Chead)
{
    __shared__ unsigned As[128 * 32];
    __shared__ unsigned Bs[32 * 72];

    int t = threadIdx.x;
    int lane = t & 31;
    int wid = t >> 5;
    int g = lane >> 2;           // 0..7
    int q = lane & 3;            // 0..3
    int warpM = (wid >> 1) * 64;
    int warpN = (wid & 1) * 32;
    int row0 = blockIdx.y * 128;
    int col0 = blockIdx.x * 64;
    int Hh = K / Chead;

    float acc[4][4][4];
    #pragma unroll
    for (int i = 0; i < 4; i++)
        #pragma unroll
        for (int j = 0; j < 4; j++)
            #pragma unroll
            for (int r = 0; r < 4; r++) acc[i][j][r] = 0.f;

    for (int k0 = 0; k0 < M; k0 += 32) {
        #pragma unroll
        for (int s = 0; s < 8; s++) {
            int idx = t + s * 128;
            int r = idx >> 3;
            int k4 = (idx & 7) * 4;
            int gr = row0 + r;
            float4 v = make_float4(0.f, 0.f, 0.f, 0.f);
            if (gr < N) v = *(const float4*)&A[(size_t)gr * M + k0 + k4];
            int sw = (k4 ^ (4 * (r & 7)));
            unsigned* p = &As[r * 32 + sw];
            p[0] = f2tf32(v.x); p[1] = f2tf32(v.y); p[2] = f2tf32(v.z); p[3] = f2tf32(v.w);
        }
        #pragma unroll
        for (int s = 0; s < 4; s++) {
            int idx = t + s * 128;
            int k = idx >> 4;
            int n4 = (idx & 15) * 4;
            float4 v = *(const float4*)&B[(size_t)(k0 + k) * K + col0 + n4];
            unsigned* p = &Bs[k * 72 + n4];
            p[0] = f2tf32(v.x); p[1] = f2tf32(v.y); p[2] = f2tf32(v.z); p[3] = f2tf32(v.w);
        }
        __syncthreads();

        #pragma unroll
        for (int kk = 0; kk < 4; kk++) {
            int kb = kk * 8;
            unsigned a[4][4], b[4][2];
            #pragma unroll
            for (int ma = 0; ma < 4; ma++) {
                int r0 = warpM + ma * 16 + g;
                int r1 = r0 + 8;
                int swz = 4 * (r0 & 7);
                a[ma][0] = As[r0 * 32 + ((kb + q)     ^ swz)];
                a[ma][1] = As[r1 * 32 + ((kb + q)     ^ swz)];
                a[ma][2] = As[r0 * 32 + ((kb + q + 4) ^ swz)];
                a[ma][3] = As[r1 * 32 + ((kb + q + 4) ^ swz)];
            }
            #pragma unroll
            for (int na = 0; na < 4; na++) {
                int c = warpN + na * 8 + g;
                b[na][0] = Bs[(kb + q)     * 72 + c];
                b[na][1] = Bs[(kb + q + 4) * 72 + c];
            }
            #pragma unroll
            for (int ma = 0; ma < 4; ma++)
                #pragma unroll
                for (int na = 0; na < 4; na++)
                    mma_tf32(acc[ma][na], a[ma], b[na]);
        }
        __syncthreads();
    }

    // ---- store C + fused score partials
    int headw = (col0 + warpN) / Chead;       // single head per warp
    int basec = (col0 + warpN) % Chead;       // channel base within head
    const float* av = atts + headw * Chead;
    const float* dv = attd + headw * Chead;

    #pragma unroll
    for (int ma = 0; ma < 4; ma++) {
        int r0 = row0 + warpM + ma * 16 + g;
        int r1 = r0 + 8;
        float s0 = 0.f, d0 = 0.f, s1 = 0.f, d1 = 0.f;
        #pragma unroll
        for (int na = 0; na < 4; na++) {
            int c = col0 + warpN + na * 8 + 2 * q;
            int ch = basec + na * 8 + 2 * q;
            float a0 = av[ch], a1 = av[ch + 1];
            float b0 = dv[ch], b1 = dv[ch + 1];
            if (r0 < N) {
                float2 v0 = make_float2(acc[ma][na][0], acc[ma][na][1]);
                *(float2*)&C[(size_t)r0 * K + c] = v0;
                s0 += v0.x * a0 + v0.y * a1;
                d0 += v0.x * b0 + v0.y * b1;
            }
            if (r1 < N) {
                float2 v1 = make_float2(acc[ma][na][2], acc[ma][na][3]);
                *(float2*)&C[(size_t)r1 * K + c] = v1;
                s1 += v1.x * a0 + v1.y * a1;
                d1 += v1.x * b0 + v1.y * b1;
            }
        }
        // reduce over q (lanes g*4 + q, q = 0..3)
        #pragma unroll
        for (int o = 1; o < 4; o <<= 1) {
            s0 += __shfl_xor_sync(0xffffffffu, s0, o);
            d0 += __shfl_xor_sync(0xffffffffu, d0, o);
            s1 += __shfl_xor_sync(0xffffffffu, s1, o);
            d1 += __shfl_xor_sync(0xffffffffu, d1, o);
        }
        if (q == 0) {
            if (r0 < N) { atomicAdd(&g_as[r0 * Hh + headw], s0); atomicAdd(&g_ad[r0 * Hh + headw], d0); }
            if (r1 < N) { atomicAdd(&g_as[r1 * Hh + headw], s1); atomicAdd(&g_ad[r1 * Hh + headw], d1); }
        }
    }
}

// ---------------- fused softmax aggregation (C=32): warp per (dst, head) ----------------
__global__ void aggregate32_kernel(const float* __restrict__ h, float* __restrict__ out,
                                   int N, int Hh)
{
    constexpr int C = 32;
    int w = (blockIdx.x * blockDim.x + threadIdx.x) >> 5;
    int lane = threadIdx.x & 31;
    if (w >= N * Hh) return;
    int dst = w / Hh, hh = w - dst * Hh;
    int beg = g_off[dst], end = g_off[dst + 1];
    float ad = g_ad[w];
    float acc = 0.f;
    float m = -INFINITY, den = 0.f;

    for (int chunk = beg; chunk < end; chunk += 32) {
        int idx = chunk + lane;
        bool valid = idx < end;
        int src = valid ? g_csr[idx] : 0;
        float e = valid ? leaky02(g_as[src * Hh + hh] + ad) : -INFINITY;
        float cm = e;
        #pragma unroll
        for (int o = 16; o; o >>= 1) cm = fmaxf(cm, __shfl_xor_sync(0xffffffffu, cm, o));
        float mn = fmaxf(m, cm);
        float scale = __expf(m - mn);
        den *= scale;
        acc *= scale;
        float ex = valid ? __expf(e - mn) : 0.f;
        float cs = ex;
        #pragma unroll
        for (int o = 16; o; o >>= 1) cs += __shfl_xor_sync(0xffffffffu, cs, o);
        den += cs;

        int cnt = min(32, end - chunk);
        int i = 0;
        for (; i + 4 <= cnt; i += 4) {
            int   s0 = __shfl_sync(0xffffffffu, src, i + 0);
            int   s1 = __shfl_sync(0xffffffffu, src, i + 1);
            int   s2 = __shfl_sync(0xffffffffu, src, i + 2);
            int   s3 = __shfl_sync(0xffffffffu, src, i + 3);
            float w0 = __shfl_sync(0xffffffffu, ex,  i + 0);
            float w1 = __shfl_sync(0xffffffffu, ex,  i + 1);
            float w2 = __shfl_sync(0xffffffffu, ex,  i + 2);
            float w3 = __shfl_sync(0xffffffffu, ex,  i + 3);
            float f0 = h[(size_t)s0 * (Hh * C) + hh * C + lane];
            float f1 = h[(size_t)s1 * (Hh * C) + hh * C + lane];
            float f2 = h[(size_t)s2 * (Hh * C) + hh * C + lane];
            float f3 = h[(size_t)s3 * (Hh * C) + hh * C + lane];
            acc += w0 * f0 + w1 * f1 + w2 * f2 + w3 * f3;
        }
        for (; i < cnt; i++) {
            int   s0 = __shfl_sync(0xffffffffu, src, i);
            float w0 = __shfl_sync(0xffffffffu, ex,  i);
            acc += w0 * h[(size_t)s0 * (Hh * C) + hh * C + lane];
        }
        m = mn;
    }
    out[(size_t)dst * (Hh * C) + hh * C + lane] = acc / (den + 1e-16f);
}

// ---------------- fused softmax aggregation (C=64): lane owns channel pair ----------------
__global__ void aggregate64_kernel(const float* __restrict__ h, float* __restrict__ out,
                                   int N, int Hh)
{
    constexpr int C = 64;
    int w = (blockIdx.x * blockDim.x + threadIdx.x) >> 5;
    int lane = threadIdx.x & 31;
    if (w >= N * Hh) return;
    int dst = w / Hh, hh = w - dst * Hh;
    int beg = g_off[dst], end = g_off[dst + 1];
    float ad = g_ad[w];
    float accx = 0.f, accy = 0.f;
    float m = -INFINITY, den = 0.f;

    for (int chunk = beg; chunk < end; chunk += 32) {
        int idx = chunk + lane;
        bool valid = idx < end;
        int src = valid ? g_csr[idx] : 0;
        float e = valid ? leaky02(g_as[src * Hh + hh] + ad) : -INFINITY;
        float cm = e;
        #pragma unroll
        for (int o = 16; o; o >>= 1) cm = fmaxf(cm, __shfl_xor_sync(0xffffffffu, cm, o));
        float mn = fmaxf(m, cm);
        float scale = __expf(m - mn);
        den *= scale;
        accx *= scale; accy *= scale;
        float ex = valid ? __expf(e - mn) : 0.f;
        float cs = ex;
        #pragma unroll
        for (int o = 16; o; o >>= 1) cs += __shfl_xor_sync(0xffffffffu, cs, o);
        den += cs;

        int cnt = min(32, end - chunk);
        int i = 0;
        for (; i + 4 <= cnt; i += 4) {
            int   s0 = __shfl_sync(0xffffffffu, src, i + 0);
            int   s1 = __shfl_sync(0xffffffffu, src, i + 1);
            int   s2 = __shfl_sync(0xffffffffu, src, i + 2);
            int   s3 = __shfl_sync(0xffffffffu, src, i + 3);
            float w0 = __shfl_sync(0xffffffffu, ex,  i + 0);
            float w1 = __shfl_sync(0xffffffffu, ex,  i + 1);
            float w2 = __shfl_sync(0xffffffffu, ex,  i + 2);
            float w3 = __shfl_sync(0xffffffffu, ex,  i + 3);
            float2 f0 = *(const float2*)&h[(size_t)s0 * (Hh * C) + hh * C + 2 * lane];
            float2 f1 = *(const float2*)&h[(size_t)s1 * (Hh * C) + hh * C + 2 * lane];
            float2 f2 = *(const float2*)&h[(size_t)s2 * (Hh * C) + hh * C + 2 * lane];
            float2 f3 = *(const float2*)&h[(size_t)s3 * (Hh * C) + hh * C + 2 * lane];
            accx += w0 * f0.x + w1 * f1.x + w2 * f2.x + w3 * f3.x;
            accy += w0 * f0.y + w1 * f1.y + w2 * f2.y + w3 * f3.y;
        }
        for (; i < cnt; i++) {
            int   s0 = __shfl_sync(0xffffffffu, src, i);
            float w0 = __shfl_sync(0xffffffffu, ex,  i);
            float2 f0 = *(const float2*)&h[(size_t)s0 * (Hh * C) + hh * C + 2 * lane];
            accx += w0 * f0.x;
            accy += w0 * f0.y;
        }
        m = mn;
    }
    float inv = 1.f / (den + 1e-16f);
    float2 o2 = make_float2(accx * inv, accy * inv);
    *(float2*)&out[(size_t)dst * (Hh * C) + hh * C + 2 * lane] = o2;
}

// ---------------- batch norm ----------------
__global__ void bn_stats_kernel(const float* __restrict__ x, int N, int F) {
    int f = threadIdx.x;   // blockDim.x == F
    float s = 0.f, q = 0.f;
    for (int n = blockIdx.x; n < N; n += gridDim.x) {
        float v = x[(size_t)n * F + f];
        s += v; q += v * v;
    }
    atomicAdd(&g_bnsum[f], s);
    atomicAdd(&g_bnsq[f], q);
}

// BN + ELU; optionally fuse global mean-pool accumulation (last layer, F must be 64)
__global__ void bn_elu_kernel(float* __restrict__ x, int N, int F,
                              const float* __restrict__ g, const float* __restrict__ bt,
                              const int* __restrict__ batch, int do_pool)
{
    int i = blockIdx.x * blockDim.x + threadIdx.x;
    if (i >= N * F) return;
    int f = i % F;
    float inv_n = 1.0f / (float)N;
    float mu = g_bnsum[f] * inv_n;
    float var = g_bnsq[f] * inv_n - mu * mu;
    float v = (x[i] - mu) * rsqrtf(var + 1e-5f) * g[f] + bt[f];
    v = v > 0.f ? v : (expf(v) - 1.f);
    x[i] = v;
    if (do_pool) {
        int n = i / F;
        int b = batch[n];
        atomicAdd(&g_pool[b * 64 + f], v);
        if (f == 0) atomicAdd(&g_cnt[b], 1.0f);
    }
}

// ---------------- MLP head: one block per graph ----------------
__global__ void mlp_kernel(const float* __restrict__ fw1, const float* __restrict__ fb1,
                           const float* __restrict__ fw2, const float* __restrict__ fb2,
                           const float* __restrict__ fw3, const float* __restrict__ fb3,
                           float* __restrict__ out)
{
    __shared__ float p[64], z1[128], z2[32];
    int gph = blockIdx.x;
    int t = threadIdx.x;   // 128 threads
    if (t < 64) p[t] = g_pool[gph * 64 + t] / fmaxf(g_cnt[gph], 1.0f);
    __syncthreads();
    float a = fb1[t];
    #pragma unroll 8
    for (int k = 0; k < 64; k++) a += p[k] * fw1[k * 128 + t];
    z1[t] = leaky02(a);
    __syncthreads();
    if (t < 32) {
        float b = fb2[t];
        #pragma unroll 8
        for (int k = 0; k < 128; k++) b += z1[k] * fw2[k * 32 + t];
        z2[t] = leaky02(b);
    }
    __syncthreads();
    if (t < 2) {
        float c = fb3[t];
        #pragma unroll
        for (int k = 0; k < 32; k++) c += z2[k] * fw3[k * 2 + t];
        out[gph * 2 + t] = c;
    }
}

// ---------------- host orchestration ----------------
static void run_gat_layer(const float* in, int Fin, const float* W,
                          const float* atts, const float* attd,
                          int Hh, int C, const float* g, const float* bt,
                          int N, const int* batch, int do_pool,
                          float* hbuf, float* obuf)
{
    int HC = Hh * C;
    int nm = N * Hh;
    layer_init_kernel<<<(nm + 255) / 256, 256>>>(nm);

    dim3 gb(HC / 64, (N + 127) / 128);
    gemm_tc_kernel<<<gb, 128>>>(in, W, hbuf, N, Fin, HC, atts, attd, C);

    if (C == 64)
        aggregate64_kernel<<<(nm * 32 + 255) / 256, 256>>>(hbuf, obuf, N, Hh);
    else
        aggregate32_kernel<<<(nm * 32 + 255) / 256, 256>>>(hbuf, obuf, N, Hh);

    bn_stats_kernel<<<256, HC>>>(obuf, N, HC);
    int nz = N * HC;
    bn_elu_kernel<<<(nz + 255) / 256, 256>>>(obuf, N, HC, g, bt, batch, do_pool);
}

extern "C" void kernel_launch(void* const* d_in, const int* in_sizes, int n_in,
                              void* d_out, int out_size)
{
    const float* x     = (const float*)d_in[0];
    const int*   ei    = (const int*)  d_in[1];
    const int*   batch = (const int*)  d_in[2];
    const float* W1  = (const float*)d_in[3];
    const float* as1 = (const float*)d_in[4];
    const float* ad1 = (const float*)d_in[5];
    const float* W2  = (const float*)d_in[7];
    const float* as2 = (const float*)d_in[8];
    const float* ad2 = (const float*)d_in[9];
    const float* W3  = (const float*)d_in[11];
    const float* as3 = (const float*)d_in[12];
    const float* ad3 = (const float*)d_in[13];
    const float* g1  = (const float*)d_in[15];
    const float* bt1 = (const float*)d_in[16];
    const float* g2  = (const float*)d_in[17];
    const float* bt2 = (const float*)d_in[18];
    const float* g3  = (const float*)d_in[19];
    const float* bt3 = (const float*)d_in[20];
    const float* fw1 = (const float*)d_in[21];
    const float* fb1 = (const float*)d_in[22];
    const float* fw2 = (const float*)d_in[23];
    const float* fb2 = (const float*)d_in[24];
    const float* fw3 = (const float*)d_in[25];
    const float* fb3 = (const float*)d_in[26];

    int N = in_sizes[0] / 128;
    int E = in_sizes[1] / 2;
    int nb = (N + 255) / 256;   // 196 <= 256

    float *hbuf, *obuf;
    cudaGetSymbolAddress((void**)&hbuf, g_h);
    cudaGetSymbolAddress((void**)&obuf, g_out);

    // --- CSR build (once per call; reused by all 3 layers) ---
    init_once_kernel<<<(N + 255) / 256, 256>>>(N);
    count_kernel<<<(E + 255) / 256, 256>>>(ei, E);
    partial_kernel<<<nb, 256>>>(N);
    bscan_kernel<<<1, 256>>>(nb);
    off_kernel<<<nb, 256>>>(N);
    selfloop_kernel<<<(N + 255) / 256, 256>>>(N);
    scatter_kernel<<<(E + 255) / 256, 256>>>(ei, E);

    // biases b1/b2/b3 cancel inside the following BatchNorm (constant per-feature
    // shift removed by mean subtraction), so they are skipped.
    run_gat_layer(x,    128, W1, as1, ad1, 4, 64, g1, bt1, N, batch, 0, hbuf, obuf);
    run_gat_layer(obuf, 256, W2, as2, ad2, 4, 32, g2, bt2, N, batch, 0, hbuf, obuf);
    run_gat_layer(obuf, 128, W3, as3, ad3, 1, 64, g3, bt3, N, batch, 1, hbuf, obuf);

    mlp_kernel<<<64, 128>>>(fw1, fb1, fw2, fb2, fw3, fb3, (float*)d_out);
}

// round 12
// speedup vs baseline: 3.9212x; 1.0051x over previous
#include <cuda_runtime.h>
#include <math.h>

// ---------------- scratch (static device globals; no allocation) ----------------
__device__ float g_h  [50000 * 256];   // post-GEMM features for current layer
__device__ float g_out[50000 * 256];   // aggregated output / next-layer input
__device__ float g_as1[50000 * 4], g_ad1[50000 * 4];
__device__ float g_as2[50000 * 4], g_ad2[50000 * 4];
__device__ float g_as3[50000 * 1], g_ad3[50000 * 1];
__device__ int   g_deg[50000];
__device__ int   g_off[50001];
__device__ int   g_cur[50000];
__device__ int   g_csr[850000];        // E + N entries (src ids, grouped by dst)
__device__ int   g_bsum[256];
__device__ int   g_tick;
__device__ float g_bnsum[3][256];
__device__ float g_bnsq [3][256];
__device__ float g_pool[64 * 64];
__device__ float g_cnt [64];

__device__ __forceinline__ float leaky02(float v) { return v > 0.f ? v : 0.2f * v; }

__device__ __forceinline__ unsigned f2tf32(float x) {
    unsigned r; asm("cvt.rna.tf32.f32 %0, %1;" : "=r"(r) : "f"(x)); return r;
}

__device__ __forceinline__ void mma_tf32(float* d, const unsigned* a, const unsigned* b) {
    asm volatile(
        "mma.sync.aligned.m16n8k8.row.col.f32.tf32.tf32.f32 "
        "{%0,%1,%2,%3}, {%4,%5,%6,%7}, {%8,%9}, {%0,%1,%2,%3};"
        : "+f"(d[0]), "+f"(d[1]), "+f"(d[2]), "+f"(d[3])
        : "r"(a[0]), "r"(a[1]), "r"(a[2]), "r"(a[3]), "r"(b[0]), "r"(b[1]));
}

__device__ __forceinline__ void cp16(float* smem, const float* gmem, bool valid) {
    unsigned saddr = (unsigned)__cvta_generic_to_shared(smem);
    int sz = valid ? 16 : 0;
    asm volatile("cp.async.ca.shared.global [%0], [%1], 16, %2;" :: "r"(saddr), "l"(gmem), "r"(sz));
}
#define CP_COMMIT() asm volatile("cp.async.commit_group;")
#define CP_WAIT0()  asm volatile("cp.async.wait_group 0;")

// ---------------- launch 0: one-time init ----------------
__global__ void init_once_kernel(int N) {
    int i = blockIdx.x * blockDim.x + threadIdx.x;
    if (i < N) { g_deg[i] = 0; g_as3[i] = 0.f; g_ad3[i] = 0.f; }
    if (i < N * 4) { g_as1[i] = 0.f; g_ad1[i] = 0.f; g_as2[i] = 0.f; g_ad2[i] = 0.f; }
    if (i < 64 * 64) g_pool[i] = 0.f;
    if (i < 64) g_cnt[i] = 0.f;
    if (i < 256) {
        for (int l = 0; l < 3; l++) { g_bnsum[l][i] = 0.f; g_bnsq[l][i] = 0.f; }
    }
    if (i == 0) g_tick = 0;
}

// ---------------- launch 1: degree count ----------------
__global__ void count_kernel(const int* __restrict__ ei, int E) {
    int e = blockIdx.x * blockDim.x + threadIdx.x;
    if (e < E) atomicAdd(&g_deg[ei[E + e]], 1);
}

// ---------------- launch 2: block partials + last-block scan of partials ----------------
__global__ void partialscan_kernel(int N, int nb) {
    __shared__ int sh[256];
    __shared__ int lastflag;
    int tid = threadIdx.x;
    int i = blockIdx.x * 256 + tid;
    sh[tid] = (i < N) ? (g_deg[i] + 1) : 0;
    __syncthreads();
    for (int o = 128; o; o >>= 1) {
        if (tid < o) sh[tid] += sh[tid + o];
        __syncthreads();
    }
    if (tid == 0) {
        g_bsum[blockIdx.x] = sh[0];
        __threadfence();
        int t = atomicAdd(&g_tick, 1);
        lastflag = (t == nb - 1);
    }
    __syncthreads();
    if (lastflag) {
        __threadfence();
        int v = (tid < nb) ? g_bsum[tid] : 0;
        sh[tid] = v;
        __syncthreads();
        for (int o = 1; o < 256; o <<= 1) {
            int t2 = (tid >= o) ? sh[tid - o] : 0;
            __syncthreads();
            sh[tid] += t2;
            __syncthreads();
        }
        if (tid < nb) g_bsum[tid] = sh[tid] - v;   // exclusive block offsets
    }
}

// ---------------- launch 3: per-node offsets (+ g_cur init) ----------------
__global__ void off_kernel(int N) {
    __shared__ int sh[256];
    int tid = threadIdx.x;
    int i = blockIdx.x * 256 + tid;
    int v = (i < N) ? (g_deg[i] + 1) : 0;
    sh[tid] = v;
    __syncthreads();
    for (int o = 1; o < 256; o <<= 1) {
        int t = (tid >= o) ? sh[tid - o] : 0;
        __syncthreads();
        sh[tid] += t;
        __syncthreads();
    }
    if (i < N) {
        g_off[i + 1] = g_bsum[blockIdx.x] + sh[tid];
        g_cur[i] = 0;
    }
    if (i == 0) g_off[0] = 0;
}

// ---------------- launch 4: self-loops + edge scatter ----------------
__global__ void loopscatter_kernel(const int* __restrict__ ei, int N, int E) {
    int i = blockIdx.x * blockDim.x + threadIdx.x;
    if (i < N) {
        g_csr[g_off[i]] = i;          // self loop first
    } else if (i < N + E) {
        int e = i - N;
        int d = ei[E + e];
        int pos = g_off[d] + 1 + atomicAdd(&g_cur[d], 1);
        g_csr[pos] = ei[e];
    }
}

// ---------------- TF32 TC GEMM, cp.async double-buffered, fused score epilogue ----------------
// C[N,K] = A[N,M] @ B[M,K]; BM=128, BN=64, BK=32; 128 threads = 4 warps, warp tile 64x32.
__global__ __launch_bounds__(128) void gemm_tc_kernel(
    const float* __restrict__ A, const float* __restrict__ B, float* __restrict__ C,
    int N, int M, int K,
    const float* __restrict__ atts, const float* __restrict__ attd, int Chead,
    float* __restrict__ asbuf, float* __restrict__ adbuf)
{
    extern __shared__ float dyn[];
    float* As = dyn;            // 2 buffers of 128*32
    float* Bs = dyn + 8192;     // 2 buffers of 32*72

    int t = threadIdx.x;
    int lane = t & 31;
    int wid = t >> 5;
    int g = lane >> 2;           // 0..7
    int q = lane & 3;            // 0..3
    int warpM = (wid >> 1) * 64;
    int warpN = (wid & 1) * 32;
    int row0 = blockIdx.y * 128;
    int col0 = blockIdx.x * 64;
    int Hh = K / Chead;

    float acc[4][4][4];
    #pragma unroll
    for (int i = 0; i < 4; i++)
        #pragma unroll
        for (int j = 0; j < 4; j++)
            #pragma unroll
            for (int r = 0; r < 4; r++) acc[i][j][r] = 0.f;

    auto issue_tile = [&](int buf, int k0) {
        float* Ab = As + buf * 4096;
        float* Bb = Bs + buf * 2304;
        #pragma unroll
        for (int s = 0; s < 8; s++) {
            int idx = t + s * 128;
            int r = idx >> 3;
            int k4 = (idx & 7) * 4;
            int gr = row0 + r;
            int sw = k4 ^ (4 * (r & 7));
            cp16(&Ab[r * 32 + sw], &A[(size_t)gr * M + k0 + k4], gr < N);
        }
        #pragma unroll
        for (int s = 0; s < 4; s++) {
            int idx = t + s * 128;
            int k = idx >> 4;
            int n4 = (idx & 15) * 4;
            cp16(&Bb[k * 72 + n4], &B[(size_t)(k0 + k) * K + col0 + n4], true);
        }
        CP_COMMIT();
    };

    int nIter = M >> 5;
    issue_tile(0, 0);

    for (int it = 0; it < nIter; it++) {
        CP_WAIT0();
        __syncthreads();
        if (it + 1 < nIter) issue_tile((it + 1) & 1, (it + 1) * 32);

        const float* Ab = As + (it & 1) * 4096;
        const float* Bb = Bs + (it & 1) * 2304;

        #pragma unroll
        for (int kk = 0; kk < 4; kk++) {
            int kb = kk * 8;
            unsigned a[4][4], b[4][2];
            #pragma unroll
            for (int ma = 0; ma < 4; ma++) {
                int r0 = warpM + ma * 16 + g;
                int r1 = r0 + 8;
                int swz = 4 * (r0 & 7);
                a[ma][0] = f2tf32(Ab[r0 * 32 + ((kb + q)     ^ swz)]);
                a[ma][1] = f2tf32(Ab[r1 * 32 + ((kb + q)     ^ swz)]);
                a[ma][2] = f2tf32(Ab[r0 * 32 + ((kb + q + 4) ^ swz)]);
                a[ma][3] = f2tf32(Ab[r1 * 32 + ((kb + q + 4) ^ swz)]);
            }
            #pragma unroll
            for (int na = 0; na < 4; na++) {
                int c = warpN + na * 8 + g;
                b[na][0] = f2tf32(Bb[(kb + q)     * 72 + c]);
                b[na][1] = f2tf32(Bb[(kb + q + 4) * 72 + c]);
            }
            #pragma unroll
            for (int ma = 0; ma < 4; ma++)
                #pragma unroll
                for (int na = 0; na < 4; na++)
                    mma_tf32(acc[ma][na], a[ma], b[na]);
        }
        __syncthreads();
    }

    // ---- store C + fused score partials (each warp's 32 cols lie in one head)
    int headw = (col0 + warpN) / Chead;
    int basec = (col0 + warpN) % Chead;
    const float* av = atts + headw * Chead;
    const float* dv = attd + headw * Chead;

    #pragma unroll
    for (int ma = 0; ma < 4; ma++) {
        int r0 = row0 + warpM + ma * 16 + g;
        int r1 = r0 + 8;
        float s0 = 0.f, d0 = 0.f, s1 = 0.f, d1 = 0.f;
        #pragma unroll
        for (int na = 0; na < 4; na++) {
            int c = col0 + warpN + na * 8 + 2 * q;
            int ch = basec + na * 8 + 2 * q;
            float a0 = av[ch], a1 = av[ch + 1];
            float b0 = dv[ch], b1 = dv[ch + 1];
            if (r0 < N) {
                float2 v0 = make_float2(acc[ma][na][0], acc[ma][na][1]);
                *(float2*)&C[(size_t)r0 * K + c] = v0;
                s0 += v0.x * a0 + v0.y * a1;
                d0 += v0.x * b0 + v0.y * b1;
            }
            if (r1 < N) {
                float2 v1 = make_float2(acc[ma][na][2], acc[ma][na][3]);
                *(float2*)&C[(size_t)r1 * K + c] = v1;
                s1 += v1.x * a0 + v1.y * a1;
                d1 += v1.x * b0 + v1.y * b1;
            }
        }
        #pragma unroll
        for (int o = 1; o < 4; o <<= 1) {
            s0 += __shfl_xor_sync(0xffffffffu, s0, o);
            d0 += __shfl_xor_sync(0xffffffffu, d0, o);
            s1 += __shfl_xor_sync(0xffffffffu, s1, o);
            d1 += __shfl_xor_sync(0xffffffffu, d1, o);
        }
        if (q == 0) {
            if (r0 < N) { atomicAdd(&asbuf[r0 * Hh + headw], s0); atomicAdd(&adbuf[r0 * Hh + headw], d0); }
            if (r1 < N) { atomicAdd(&asbuf[r1 * Hh + headw], s1); atomicAdd(&adbuf[r1 * Hh + headw], d1); }
        }
    }
}

// ---------------- fused softmax aggregation (C=32): warp per (dst, head) ----------------
__global__ void aggregate32_kernel(const float* __restrict__ h, float* __restrict__ out,
                                   int N, int Hh,
                                   const float* __restrict__ asbuf, const float* __restrict__ adbuf)
{
    constexpr int C = 32;
    int w = (blockIdx.x * blockDim.x + threadIdx.x) >> 5;
    int lane = threadIdx.x & 31;
    if (w >= N * Hh) return;
    int dst = w / Hh, hh = w - dst * Hh;
    int beg = g_off[dst], end = g_off[dst + 1];
    float ad = adbuf[w];
    float acc = 0.f;
    float m = -INFINITY, den = 0.f;

    for (int chunk = beg; chunk < end; chunk += 32) {
        int idx = chunk + lane;
        bool valid = idx < end;
        int src = valid ? g_csr[idx] : 0;
        float e = valid ? leaky02(asbuf[src * Hh + hh] + ad) : -INFINITY;
        float cm = e;
        #pragma unroll
        for (int o = 16; o; o >>= 1) cm = fmaxf(cm, __shfl_xor_sync(0xffffffffu, cm, o));
        float mn = fmaxf(m, cm);
        float scale = __expf(m - mn);
        den *= scale;
        acc *= scale;
        float ex = valid ? __expf(e - mn) : 0.f;
        float cs = ex;
        #pragma unroll
        for (int o = 16; o; o >>= 1) cs += __shfl_xor_sync(0xffffffffu, cs, o);
        den += cs;

        int cnt = min(32, end - chunk);
        int i = 0;
        for (; i + 4 <= cnt; i += 4) {
            int   s0 = __shfl_sync(0xffffffffu, src, i + 0);
            int   s1 = __shfl_sync(0xffffffffu, src, i + 1);
            int   s2 = __shfl_sync(0xffffffffu, src, i + 2);
            int   s3 = __shfl_sync(0xffffffffu, src, i + 3);
            float w0 = __shfl_sync(0xffffffffu, ex,  i + 0);
            float w1 = __shfl_sync(0xffffffffu, ex,  i + 1);
            float w2 = __shfl_sync(0xffffffffu, ex,  i + 2);
            float w3 = __shfl_sync(0xffffffffu, ex,  i + 3);
            float f0 = h[(size_t)s0 * (Hh * C) + hh * C + lane];
            float f1 = h[(size_t)s1 * (Hh * C) + hh * C + lane];
            float f2 = h[(size_t)s2 * (Hh * C) + hh * C + lane];
            float f3 = h[(size_t)s3 * (Hh * C) + hh * C + lane];
            acc += w0 * f0 + w1 * f1 + w2 * f2 + w3 * f3;
        }
        for (; i < cnt; i++) {
            int   s0 = __shfl_sync(0xffffffffu, src, i);
            float w0 = __shfl_sync(0xffffffffu, ex,  i);
            acc += w0 * h[(size_t)s0 * (Hh * C) + hh * C + lane];
        }
        m = mn;
    }
    out[(size_t)dst * (Hh * C) + hh * C + lane] = acc / (den + 1e-16f);
}

// ---------------- fused softmax aggregation (C=64): lane owns channel pair ----------------
__global__ void aggregate64_kernel(const float* __restrict__ h, float* __restrict__ out,
                                   int N, int Hh,
                                   const float* __restrict__ asbuf, const float* __restrict__ adbuf)
{
    constexpr int C = 64;
    int w = (blockIdx.x * blockDim.x + threadIdx.x) >> 5;
    int lane = threadIdx.x & 31;
    if (w >= N * Hh) return;
    int dst = w / Hh, hh = w - dst * Hh;
    int beg = g_off[dst], end = g_off[dst + 1];
    float ad = adbuf[w];
    float accx = 0.f, accy = 0.f;
    float m = -INFINITY, den = 0.f;

    for (int chunk = beg; chunk < end; chunk += 32) {
        int idx = chunk + lane;
        bool valid = idx < end;
        int src = valid ? g_csr[idx] : 0;
        float e = valid ? leaky02(asbuf[src * Hh + hh] + ad) : -INFINITY;
        float cm = e;
        #pragma unroll
        for (int o = 16; o; o >>= 1) cm = fmaxf(cm, __shfl_xor_sync(0xffffffffu, cm, o));
        float mn = fmaxf(m, cm);
        float scale = __expf(m - mn);
        den *= scale;
        accx *= scale; accy *= scale;
        float ex = valid ? __expf(e - mn) : 0.f;
        float cs = ex;
        #pragma unroll
        for (int o = 16; o; o >>= 1) cs += __shfl_xor_sync(0xffffffffu, cs, o);
        den += cs;

        int cnt = min(32, end - chunk);
        int i = 0;
        for (; i + 4 <= cnt; i += 4) {
            int   s0 = __shfl_sync(0xffffffffu, src, i + 0);
            int   s1 = __shfl_sync(0xffffffffu, src, i + 1);
            int   s2 = __shfl_sync(0xffffffffu, src, i + 2);
            int   s3 = __shfl_sync(0xffffffffu, src, i + 3);
            float w0 = __shfl_sync(0xffffffffu, ex,  i + 0);
            float w1 = __shfl_sync(0xffffffffu, ex,  i + 1);
            float w2 = __shfl_sync(0xffffffffu, ex,  i + 2);
            float w3 = __shfl_sync(0xffffffffu, ex,  i + 3);
            float2 f0 = *(const float2*)&h[(size_t)s0 * (Hh * C) + hh * C + 2 * lane];
            float2 f1 = *(const float2*)&h[(size_t)s1 * (Hh * C) + hh * C + 2 * lane];
            float2 f2 = *(const float2*)&h[(size_t)s2 * (Hh * C) + hh * C + 2 * lane];
            float2 f3 = *(const float2*)&h[(size_t)s3 * (Hh * C) + hh * C + 2 * lane];
            accx += w0 * f0.x + w1 * f1.x + w2 * f2.x + w3 * f3.x;
            accy += w0 * f0.y + w1 * f1.y + w2 * f2.y + w3 * f3.y;
        }
        for (; i < cnt; i++) {
            int   s0 = __shfl_sync(0xffffffffu, src, i);
            float w0 = __shfl_sync(0xffffffffu, ex,  i);
            float2 f0 = *(const float2*)&h[(size_t)s0 * (Hh * C) + hh * C + 2 * lane];
            accx += w0 * f0.x;
            accy += w0 * f0.y;
        }
        m = mn;
    }
    float inv = 1.f / (den + 1e-16f);
    float2 o2 = make_float2(accx * inv, accy * inv);
    *(float2*)&out[(size_t)dst * (Hh * C) + hh * C + 2 * lane] = o2;
}

// ---------------- batch norm ----------------
__global__ void bn_stats_kernel(const float* __restrict__ x, int N, int F, int slot) {
    int f = threadIdx.x;   // blockDim.x == F
    float s = 0.f, q = 0.f;
    for (int n = blockIdx.x; n < N; n += gridDim.x) {
        float v = x[(size_t)n * F + f];
        s += v; q += v * v;
    }
    atomicAdd(&g_bnsum[slot][f], s);
    atomicAdd(&g_bnsq[slot][f], q);
}

// BN + ELU; optionally fuse global mean-pool accumulation (last layer, F == 64)
__global__ void bn_elu_kernel(float* __restrict__ x, int N, int F, int slot,
                              const float* __restrict__ g, const float* __restrict__ bt,
                              const int* __restrict__ batch, int do_pool)
{
    int i = blockIdx.x * blockDim.x + threadIdx.x;
    if (i >= N * F) return;
    int f = i % F;
    float inv_n = 1.0f / (float)N;
    float mu = g_bnsum[slot][f] * inv_n;
    float var = g_bnsq[slot][f] * inv_n - mu * mu;
    float v = (x[i] - mu) * rsqrtf(var + 1e-5f) * g[f] + bt[f];
    v = v > 0.f ? v : (expf(v) - 1.f);
    x[i] = v;
    if (do_pool) {
        int n = i / F;
        int b = batch[n];
        atomicAdd(&g_pool[b * 64 + f], v);
        if (f == 0) atomicAdd(&g_cnt[b], 1.0f);
    }
}

// ---------------- MLP head: one block per graph ----------------
__global__ void mlp_kernel(const float* __restrict__ fw1, const float* __restrict__ fb1,
                           const float* __restrict__ fw2, const float* __restrict__ fb2,
                           const float* __restrict__ fw3, const float* __restrict__ fb3,
                           float* __restrict__ out)
{
    __shared__ float p[64], z1[128], z2[32];
    int gph = blockIdx.x;
    int t = threadIdx.x;   // 128 threads
    if (t < 64) p[t] = g_pool[gph * 64 + t] / fmaxf(g_cnt[gph], 1.0f);
    __syncthreads();
    float a = fb1[t];
    #pragma unroll 8
    for (int k = 0; k < 64; k++) a += p[k] * fw1[k * 128 + t];
    z1[t] = leaky02(a);
    __syncthreads();
    if (t < 32) {
        float b = fb2[t];
        #pragma unroll 8
        for (int k = 0; k < 128; k++) b += z1[k] * fw2[k * 32 + t];
        z2[t] = leaky02(b);
    }
    __syncthreads();
    if (t < 2) {
        float c = fb3[t];
        #pragma unroll
        for (int k = 0; k < 32; k++) c += z2[k] * fw3[k * 2 + t];
        out[gph * 2 + t] = c;
    }
}

// ---------------- host orchestration ----------------
static const int GEMM_DYN_SMEM = (8192 + 2 * 2304) * 4;   // 50.7KB

static void run_gat_layer(const float* in, int Fin, const float* W,
                          const float* atts, const float* attd,
                          int Hh, int C, const float* g, const float* bt,
                          int N, const int* batch, int do_pool, int slot,
                          float* asbuf, float* adbuf,
                          float* hbuf, float* obuf)
{
    int HC = Hh * C;
    int nm = N * Hh;

    dim3 gb(HC / 64, (N + 127) / 128);
    gemm_tc_kernel<<<gb, 128, GEMM_DYN_SMEM>>>(in, W, hbuf, N, Fin, HC, atts, attd, C,
                                               asbuf, adbuf);

    if (C == 64)
        aggregate64_kernel<<<(nm * 32 + 255) / 256, 256>>>(hbuf, obuf, N, Hh, asbuf, adbuf);
    else
        aggregate32_kernel<<<(nm * 32 + 255) / 256, 256>>>(hbuf, obuf, N, Hh, asbuf, adbuf);

    bn_stats_kernel<<<256, HC>>>(obuf, N, HC, slot);
    int nz = N * HC;
    bn_elu_kernel<<<(nz + 255) / 256, 256>>>(obuf, N, HC, slot, g, bt, batch, do_pool);
}

extern "C" void kernel_launch(void* const* d_in, const int* in_sizes, int n_in,
                              void* d_out, int out_size)
{
    const float* x     = (const float*)d_in[0];
    const int*   ei    = (const int*)  d_in[1];
    const int*   batch = (const int*)  d_in[2];
    const float* W1  = (const float*)d_in[3];
    const float* as1 = (const float*)d_in[4];
    const float* ad1 = (const float*)d_in[5];
    const float* W2  = (const float*)d_in[7];
    const float* as2 = (const float*)d_in[8];
    const float* ad2 = (const float*)d_in[9];
    const float* W3  = (const float*)d_in[11];
    const float* as3 = (const float*)d_in[12];
    const float* ad3 = (const float*)d_in[13];
    const float* g1  = (const float*)d_in[15];
    const float* bt1 = (const float*)d_in[16];
    const float* g2  = (const float*)d_in[17];
    const float* bt2 = (const float*)d_in[18];
    const float* g3  = (const float*)d_in[19];
    const float* bt3 = (const float*)d_in[20];
    const float* fw1 = (const float*)d_in[21];
    const float* fb1 = (const float*)d_in[22];
    const float* fw2 = (const float*)d_in[23];
    const float* fb2 = (const float*)d_in[24];
    const float* fw3 = (const float*)d_in[25];
    const float* fb3 = (const float*)d_in[26];

    int N = in_sizes[0] / 128;
    int E = in_sizes[1] / 2;
    int nb = (N + 255) / 256;   // 196 <= 256

    cudaFuncSetAttribute(gemm_tc_kernel, cudaFuncAttributeMaxDynamicSharedMemorySize,
                         GEMM_DYN_SMEM);

    float *hbuf, *obuf;
    cudaGetSymbolAddress((void**)&hbuf, g_h);
    cudaGetSymbolAddress((void**)&obuf, g_out);
    float *pas1, *pad1, *pas2, *pad2, *pas3, *pad3;
    cudaGetSymbolAddress((void**)&pas1, g_as1);
    cudaGetSymbolAddress((void**)&pad1, g_ad1);
    cudaGetSymbolAddress((void**)&pas2, g_as2);
    cudaGetSymbolAddress((void**)&pad2, g_ad2);
    cudaGetSymbolAddress((void**)&pas3, g_as3);
    cudaGetSymbolAddress((void**)&pad3, g_ad3);

    // --- CSR build: exactly 5 launches, so the GEMM lands in ncu's -s 5 slot ---
    init_once_kernel<<<(N * 4 + 255) / 256, 256>>>(N);
    count_kernel<<<(E + 255) / 256, 256>>>(ei, E);
    partialscan_kernel<<<nb, 256>>>(N, nb);
    off_kernel<<<nb, 256>>>(N);
    loopscatter_kernel<<<(N + E + 255) / 256, 256>>>(ei, N, E);

    // biases b1/b2/b3 cancel inside the following BatchNorm.
    run_gat_layer(x,    128, W1, as1, ad1, 4, 64, g1, bt1, N, batch, 0, 0, pas1, pad1, hbuf, obuf);
    run_gat_layer(obuf, 256, W2, as2, ad2, 4, 32, g2, bt2, N, batch, 0, 1, pas2, pad2, hbuf, obuf);
    run_gat_layer(obuf, 128, W3, as3, ad3, 1, 64, g3, bt3, N, batch, 1, 2, pas3, pad3, hbuf, obuf);

    mlp_kernel<<<64, 128>>>(fw1, fb1, fw2, fb2, fw3, fb3, (float*)d_out);
}

// round 15
// speedup vs baseline: 5.7732x; 1.4723x over previous
#include <cuda_runtime.h>
#include <math.h>

// ---------------- scratch (static device globals; no allocation) ----------------
__device__ float g_h  [50000 * 256];
__device__ float g_out[50000 * 256];
__device__ __align__(16) float g_as1[50000 * 4];
__device__ __align__(16) float g_ad1[50000 * 4];
__device__ __align__(16) float g_as2[50000 * 4];
__device__ __align__(16) float g_ad2[50000 * 4];
__device__ float g_as3[50000], g_ad3[50000];
__device__ int   g_deg[50000];
__device__ int   g_off[50001];
__device__ int   g_cur[50000];
__device__ int   g_csr[850000];
__device__ int   g_bsum[256];
__device__ int   g_tick;
__device__ float g_bnsum[3][256];
__device__ float g_bnsq [3][256];
__device__ float g_pool[64 * 64];
__device__ float g_cnt [64];

__device__ __forceinline__ float leaky02(float v) { return v > 0.f ? v : 0.2f * v; }

__device__ __forceinline__ unsigned f2tf32(float x) {
    unsigned r; asm("cvt.rna.tf32.f32 %0, %1;" : "=r"(r) : "f"(x)); return r;
}

__device__ __forceinline__ void mma_tf32(float* d, const unsigned* a, const unsigned* b) {
    asm volatile(
        "mma.sync.aligned.m16n8k8.row.col.f32.tf32.tf32.f32 "
        "{%0,%1,%2,%3}, {%4,%5,%6,%7}, {%8,%9}, {%0,%1,%2,%3};"
        : "+f"(d[0]), "+f"(d[1]), "+f"(d[2]), "+f"(d[3])
        : "r"(a[0]), "r"(a[1]), "r"(a[2]), "r"(a[3]), "r"(b[0]), "r"(b[1]));
}

__device__ __forceinline__ void cp16(float* smem, const float* gmem, bool valid) {
    unsigned saddr = (unsigned)__cvta_generic_to_shared(smem);
    int sz = valid ? 16 : 0;
    asm volatile("cp.async.ca.shared.global [%0], [%1], 16, %2;" :: "r"(saddr), "l"(gmem), "r"(sz));
}
#define CP_COMMIT() asm volatile("cp.async.commit_group;")
#define CP_WAIT0()  asm volatile("cp.async.wait_group 0;")

// ---------------- launch 0: one-time init ----------------
__global__ void init_once_kernel(int N) {
    int i = blockIdx.x * blockDim.x + threadIdx.x;
    if (i < N) { g_deg[i] = 0; g_as3[i] = 0.f; g_ad3[i] = 0.f; }
    if (i < N * 4) { g_as1[i] = 0.f; g_ad1[i] = 0.f; g_as2[i] = 0.f; g_ad2[i] = 0.f; }
    if (i < 64 * 64) g_pool[i] = 0.f;
    if (i < 64) g_cnt[i] = 0.f;
    if (i < 256) {
        for (int l = 0; l < 3; l++) { g_bnsum[l][i] = 0.f; g_bnsq[l][i] = 0.f; }
    }
    if (i == 0) g_tick = 0;
}

// ---------------- launch 1: degree count ----------------
__global__ void count_kernel(const int* __restrict__ ei, int E) {
    int e = blockIdx.x * blockDim.x + threadIdx.x;
    if (e < E) atomicAdd(&g_deg[ei[E + e]], 1);
}

// ---------------- launch 2: block partials + last-block scan ----------------
__global__ void partialscan_kernel(int N, int nb) {
    __shared__ int sh[256];
    __shared__ int lastflag;
    int tid = threadIdx.x;
    int i = blockIdx.x * 256 + tid;
    sh[tid] = (i < N) ? (g_deg[i] + 1) : 0;
    __syncthreads();
    for (int o = 128; o; o >>= 1) {
        if (tid < o) sh[tid] += sh[tid + o];
        __syncthreads();
    }
    if (tid == 0) {
        g_bsum[blockIdx.x] = sh[0];
        __threadfence();
        int t = atomicAdd(&g_tick, 1);
        lastflag = (t == nb - 1);
    }
    __syncthreads();
    if (lastflag) {
        __threadfence();
        int v = (tid < nb) ? g_bsum[tid] : 0;
        sh[tid] = v;
        __syncthreads();
        for (int o = 1; o < 256; o <<= 1) {
            int t2 = (tid >= o) ? sh[tid - o] : 0;
            __syncthreads();
            sh[tid] += t2;
            __syncthreads();
        }
        if (tid < nb) g_bsum[tid] = sh[tid] - v;
    }
}

// ---------------- launch 3: per-node offsets (+ g_cur init) ----------------
__global__ void off_kernel(int N) {
    __shared__ int sh[256];
    int tid = threadIdx.x;
    int i = blockIdx.x * 256 + tid;
    int v = (i < N) ? (g_deg[i] + 1) : 0;
    sh[tid] = v;
    __syncthreads();
    for (int o = 1; o < 256; o <<= 1) {
        int t = (tid >= o) ? sh[tid - o] : 0;
        __syncthreads();
        sh[tid] += t;
        __syncthreads();
    }
    if (i < N) {
        g_off[i + 1] = g_bsum[blockIdx.x] + sh[tid];
        g_cur[i] = 0;
    }
    if (i == 0) g_off[0] = 0;
}

// ---------------- launch 4: self-loops + edge scatter ----------------
__global__ void loopscatter_kernel(const int* __restrict__ ei, int N, int E) {
    int i = blockIdx.x * blockDim.x + threadIdx.x;
    if (i < N) {
        g_csr[g_off[i]] = i;
    } else if (i < N + E) {
        int e = i - N;
        int d = ei[E + e];
        int pos = g_off[d] + 1 + atomicAdd(&g_cur[d], 1);
        g_csr[pos] = ei[e];
    }
}

// ---------------- TF32 TC GEMM, cp.async double-buffered, fused score epilogue ----------------
__global__ __launch_bounds__(128) void gemm_tc_kernel(
    const float* __restrict__ A, const float* __restrict__ B, float* __restrict__ C,
    int N, int M, int K,
    const float* __restrict__ atts, const float* __restrict__ attd, int Chead,
    float* __restrict__ asbuf, float* __restrict__ adbuf)
{
    extern __shared__ float dyn[];
    float* As = dyn;
    float* Bs = dyn + 8192;

    int t = threadIdx.x;
    int lane = t & 31;
    int wid = t >> 5;
    int g = lane >> 2;
    int q = lane & 3;
    int warpM = (wid >> 1) * 64;
    int warpN = (wid & 1) * 32;
    int row0 = blockIdx.y * 128;
    int col0 = blockIdx.x * 64;
    int Hh = K / Chead;

    float acc[4][4][4];
    #pragma unroll
    for (int i = 0; i < 4; i++)
        #pragma unroll
        for (int j = 0; j < 4; j++)
            #pragma unroll
            for (int r = 0; r < 4; r++) acc[i][j][r] = 0.f;

    auto issue_tile = [&](int buf, int k0) {
        float* Ab = As + buf * 4096;
        float* Bb = Bs + buf * 2304;
        #pragma unroll
        for (int s = 0; s < 8; s++) {
            int idx = t + s * 128;
            int r = idx >> 3;
            int k4 = (idx & 7) * 4;
            int gr = row0 + r;
            int sw = k4 ^ (4 * (r & 7));
            cp16(&Ab[r * 32 + sw], &A[(size_t)gr * M + k0 + k4], gr < N);
        }
        #pragma unroll
        for (int s = 0; s < 4; s++) {
            int idx = t + s * 128;
            int k = idx >> 4;
            int n4 = (idx & 15) * 4;
            cp16(&Bb[k * 72 + n4], &B[(size_t)(k0 + k) * K + col0 + n4], true);
        }
        CP_COMMIT();
    };

    int nIter = M >> 5;
    issue_tile(0, 0);

    for (int it = 0; it < nIter; it++) {
        CP_WAIT0();
        __syncthreads();
        if (it + 1 < nIter) issue_tile((it + 1) & 1, (it + 1) * 32);

        const float* Ab = As + (it & 1) * 4096;
        const float* Bb = Bs + (it & 1) * 2304;

        #pragma unroll
        for (int kk = 0; kk < 4; kk++) {
            int kb = kk * 8;
            unsigned a[4][4], b[4][2];
            #pragma unroll
            for (int ma = 0; ma < 4; ma++) {
                int r0 = warpM + ma * 16 + g;
                int r1 = r0 + 8;
                int swz = 4 * (r0 & 7);
                a[ma][0] = f2tf32(Ab[r0 * 32 + ((kb + q)     ^ swz)]);
                a[ma][1] = f2tf32(Ab[r1 * 32 + ((kb + q)     ^ swz)]);
                a[ma][2] = f2tf32(Ab[r0 * 32 + ((kb + q + 4) ^ swz)]);
                a[ma][3] = f2tf32(Ab[r1 * 32 + ((kb + q + 4) ^ swz)]);
            }
            #pragma unroll
            for (int na = 0; na < 4; na++) {
                int c = warpN + na * 8 + g;
                b[na][0] = f2tf32(Bb[(kb + q)     * 72 + c]);
                b[na][1] = f2tf32(Bb[(kb + q + 4) * 72 + c]);
            }
            #pragma unroll
            for (int ma = 0; ma < 4; ma++)
                #pragma unroll
                for (int na = 0; na < 4; na++)
                    mma_tf32(acc[ma][na], a[ma], b[na]);
        }
        __syncthreads();
    }

    int headw = (col0 + warpN) / Chead;
    int basec = (col0 + warpN) % Chead;
    const float* av = atts + headw * Chead;
    const float* dv = attd + headw * Chead;

    #pragma unroll
    for (int ma = 0; ma < 4; ma++) {
        int r0 = row0 + warpM + ma * 16 + g;
        int r1 = r0 + 8;
        float s0 = 0.f, d0 = 0.f, s1 = 0.f, d1 = 0.f;
        #pragma unroll
        for (int na = 0; na < 4; na++) {
            int c = col0 + warpN + na * 8 + 2 * q;
            int ch = basec + na * 8 + 2 * q;
            float a0 = av[ch], a1 = av[ch + 1];
            float b0 = dv[ch], b1 = dv[ch + 1];
            if (r0 < N) {
                float2 v0 = make_float2(acc[ma][na][0], acc[ma][na][1]);
                *(float2*)&C[(size_t)r0 * K + c] = v0;
                s0 += v0.x * a0 + v0.y * a1;
                d0 += v0.x * b0 + v0.y * b1;
            }
            if (r1 < N) {
                float2 v1 = make_float2(acc[ma][na][2], acc[ma][na][3]);
                *(float2*)&C[(size_t)r1 * K + c] = v1;
                s1 += v1.x * a0 + v1.y * a1;
                d1 += v1.x * b0 + v1.y * b1;
            }
        }
        #pragma unroll
        for (int o = 1; o < 4; o <<= 1) {
            s0 += __shfl_xor_sync(0xffffffffu, s0, o);
            d0 += __shfl_xor_sync(0xffffffffu, d0, o);
            s1 += __shfl_xor_sync(0xffffffffu, s1, o);
            d1 += __shfl_xor_sync(0xffffffffu, d1, o);
        }
        if (q == 0) {
            if (r0 < N) { atomicAdd(&asbuf[r0 * Hh + headw], s0); atomicAdd(&adbuf[r0 * Hh + headw], d0); }
            if (r1 < N) { atomicAdd(&asbuf[r1 * Hh + headw], s1); atomicAdd(&adbuf[r1 * Hh + headw], d1); }
        }
    }
}

// ---------------- merged-head aggregation (Hh=4), fused BN stats ----------------
// One warp per dst node, all 4 heads. Lane owns HC/32 channels (as float4s).
template <int C>   // C = 64 (HC=256) or 32 (HC=128)
__global__ void aggregateH4_kernel(const float* __restrict__ h, float* __restrict__ out,
                                   int N,
                                   const float4* __restrict__ as4,
                                   const float4* __restrict__ ad4, int slot)
{
    constexpr int HC = 4 * C;
    constexpr int NV = HC / 128;           // float4s per lane: 2 (C=64) or 1 (C=32)
    __shared__ float sh_sum[HC], sh_sq[HC];
    for (int i = threadIdx.x; i < HC; i += 256) { sh_sum[i] = 0.f; sh_sq[i] = 0.f; }
    __syncthreads();

    int dst = (blockIdx.x * 256 + threadIdx.x) >> 5;
    int lane = threadIdx.x & 31;

    if (dst < N) {
        int beg = g_off[dst], end = g_off[dst + 1];
        float4 adv = ad4[dst];
        float acc[NV][4];
        #pragma unroll
        for (int v = 0; v < NV; v++)
            #pragma unroll
            for (int j = 0; j < 4; j++) acc[v][j] = 0.f;
        float m[4]   = {-INFINITY, -INFINITY, -INFINITY, -INFINITY};
        float den[4] = {0.f, 0.f, 0.f, 0.f};
        // head owned by each float4 of this lane
        int hv[NV];
        #pragma unroll
        for (int v = 0; v < NV; v++) hv[v] = (v * 128 + lane * 4) / C;

        for (int chunk = beg; chunk < end; chunk += 32) {
            int idx = chunk + lane;
            bool valid = idx < end;
            int src = valid ? g_csr[idx] : 0;
            float4 sv = as4[src];
            float e[4];
            e[0] = valid ? leaky02(sv.x + adv.x) : -INFINITY;
            e[1] = valid ? leaky02(sv.y + adv.y) : -INFINITY;
            e[2] = valid ? leaky02(sv.z + adv.z) : -INFINITY;
            e[3] = valid ? leaky02(sv.w + adv.w) : -INFINITY;

            float ex[4], scale[4];
            #pragma unroll
            for (int hh = 0; hh < 4; hh++) {
                float cm = e[hh];
                #pragma unroll
                for (int o = 16; o; o >>= 1) cm = fmaxf(cm, __shfl_xor_sync(0xffffffffu, cm, o));
                float mn = fmaxf(m[hh], cm);
                scale[hh] = __expf(m[hh] - mn);
                den[hh] *= scale[hh];
                ex[hh] = valid ? __expf(e[hh] - mn) : 0.f;
                float cs = ex[hh];
                #pragma unroll
                for (int o = 16; o; o >>= 1) cs += __shfl_xor_sync(0xffffffffu, cs, o);
                den[hh] += cs;
                m[hh] = mn;
            }
            #pragma unroll
            for (int v = 0; v < NV; v++) {
                float s = scale[hv[v]];
                #pragma unroll
                for (int j = 0; j < 4; j++) acc[v][j] *= s;
            }

            int cnt = min(32, end - chunk);
            if (C == 64) {
                int i = 0;
                for (; i + 2 <= cnt; i += 2) {
                    int sA = __shfl_sync(0xffffffffu, src, i);
                    int sB = __shfl_sync(0xffffffffu, src, i + 1);
                    float a0 = __shfl_sync(0xffffffffu, ex[0], i);
                    float a1 = __shfl_sync(0xffffffffu, ex[1], i);
                    float a2 = __shfl_sync(0xffffffffu, ex[2], i);
                    float a3 = __shfl_sync(0xffffffffu, ex[3], i);
                    float b0 = __shfl_sync(0xffffffffu, ex[0], i + 1);
                    float b1 = __shfl_sync(0xffffffffu, ex[1], i + 1);
                    float b2 = __shfl_sync(0xffffffffu, ex[2], i + 1);
                    float b3 = __shfl_sync(0xffffffffu, ex[3], i + 1);
                    bool hi = lane >= 16;
                    float wA0 = hi ? a1 : a0, wA1 = hi ? a3 : a2;
                    float wB0 = hi ? b1 : b0, wB1 = hi ? b3 : b2;
                    const float4* pA = (const float4*)(h + (size_t)sA * 256);
                    const float4* pB = (const float4*)(h + (size_t)sB * 256);
                    float4 fA0 = pA[lane], fA1 = pA[32 + lane];
                    float4 fB0 = pB[lane], fB1 = pB[32 + lane];
                    acc[0][0] += wA0 * fA0.x + wB0 * fB0.x;
                    acc[0][1] += wA0 * fA0.y + wB0 * fB0.y;
                    acc[0][2] += wA0 * fA0.z + wB0 * fB0.z;
                    acc[0][3] += wA0 * fA0.w + wB0 * fB0.w;
                    acc[NV-1][0] += wA1 * fA1.x + wB1 * fB1.x;
                    acc[NV-1][1] += wA1 * fA1.y + wB1 * fB1.y;
                    acc[NV-1][2] += wA1 * fA1.z + wB1 * fB1.z;
                    acc[NV-1][3] += wA1 * fA1.w + wB1 * fB1.w;
                }
                for (; i < cnt; i++) {
                    int sA = __shfl_sync(0xffffffffu, src, i);
                    float a0 = __shfl_sync(0xffffffffu, ex[0], i);
                    float a1 = __shfl_sync(0xffffffffu, ex[1], i);
                    float a2 = __shfl_sync(0xffffffffu, ex[2], i);
                    float a3 = __shfl_sync(0xffffffffu, ex[3], i);
                    bool hi = lane >= 16;
                    float wA0 = hi ? a1 : a0, wA1 = hi ? a3 : a2;
                    const float4* pA = (const float4*)(h + (size_t)sA * 256);
                    float4 fA0 = pA[lane], fA1 = pA[32 + lane];
                    acc[0][0] += wA0 * fA0.x;
                    acc[0][1] += wA0 * fA0.y;
                    acc[0][2] += wA0 * fA0.z;
                    acc[0][3] += wA0 * fA0.w;
                    acc[NV-1][0] += wA1 * fA1.x;
                    acc[NV-1][1] += wA1 * fA1.y;
                    acc[NV-1][2] += wA1 * fA1.z;
                    acc[NV-1][3] += wA1 * fA1.w;
                }
            } else {  // C == 32, NV == 1
                int hh0 = lane >> 3;
                int i = 0;
                for (; i + 2 <= cnt; i += 2) {
                    int sA = __shfl_sync(0xffffffffu, src, i);
                    int sB = __shfl_sync(0xffffffffu, src, i + 1);
                    float a0 = __shfl_sync(0xffffffffu, ex[0], i);
                    float a1 = __shfl_sync(0xffffffffu, ex[1], i);
                    float a2 = __shfl_sync(0xffffffffu, ex[2], i);
                    float a3 = __shfl_sync(0xffffffffu, ex[3], i);
                    float b0 = __shfl_sync(0xffffffffu, ex[0], i + 1);
                    float b1 = __shfl_sync(0xffffffffu, ex[1], i + 1);
                    float b2 = __shfl_sync(0xffffffffu, ex[2], i + 1);
                    float b3 = __shfl_sync(0xffffffffu, ex[3], i + 1);
                    float wA = hh0 < 2 ? (hh0 == 0 ? a0 : a1) : (hh0 == 2 ? a2 : a3);
                    float wB = hh0 < 2 ? (hh0 == 0 ? b0 : b1) : (hh0 == 2 ? b2 : b3);
                    float4 fA = ((const float4*)(h + (size_t)sA * 128))[lane];
                    float4 fB = ((const float4*)(h + (size_t)sB * 128))[lane];
                    acc[0][0] += wA * fA.x + wB * fB.x;
                    acc[0][1] += wA * fA.y + wB * fB.y;
                    acc[0][2] += wA * fA.z + wB * fB.z;
                    acc[0][3] += wA * fA.w + wB * fB.w;
                }
                for (; i < cnt; i++) {
                    int sA = __shfl_sync(0xffffffffu, src, i);
                    float a0 = __shfl_sync(0xffffffffu, ex[0], i);
                    float a1 = __shfl_sync(0xffffffffu, ex[1], i);
                    float a2 = __shfl_sync(0xffffffffu, ex[2], i);
                    float a3 = __shfl_sync(0xffffffffu, ex[3], i);
                    float wA = hh0 < 2 ? (hh0 == 0 ? a0 : a1) : (hh0 == 2 ? a2 : a3);
                    float4 fA = ((const float4*)(h + (size_t)sA * 128))[lane];
                    acc[0][0] += wA * fA.x;
                    acc[0][1] += wA * fA.y;
                    acc[0][2] += wA * fA.z;
                    acc[0][3] += wA * fA.w;
                }
            }
        }

        #pragma unroll
        for (int v = 0; v < NV; v++) {
            float inv = 1.f / (den[hv[v]] + 1e-16f);
            float4 o4;
            o4.x = acc[v][0] * inv; o4.y = acc[v][1] * inv;
            o4.z = acc[v][2] * inv; o4.w = acc[v][3] * inv;
            int cb = v * 128 + lane * 4;
            *(float4*)&out[(size_t)dst * HC + cb] = o4;
            atomicAdd(&sh_sum[cb + 0], o4.x); atomicAdd(&sh_sq[cb + 0], o4.x * o4.x);
            atomicAdd(&sh_sum[cb + 1], o4.y); atomicAdd(&sh_sq[cb + 1], o4.y * o4.y);
            atomicAdd(&sh_sum[cb + 2], o4.z); atomicAdd(&sh_sq[cb + 2], o4.z * o4.z);
            atomicAdd(&sh_sum[cb + 3], o4.w); atomicAdd(&sh_sq[cb + 3], o4.w * o4.w);
        }
    }
    __syncthreads();
    for (int i = threadIdx.x; i < HC; i += 256) {
        atomicAdd(&g_bnsum[slot][i], sh_sum[i]);
        atomicAdd(&g_bnsq[slot][i], sh_sq[i]);
    }
}

// ---------------- aggregation for Hh=1, C=64 (layer 3), fused BN stats ----------------
__global__ void aggregate64_kernel(const float* __restrict__ h, float* __restrict__ out,
                                   int N,
                                   const float* __restrict__ asbuf, const float* __restrict__ adbuf,
                                   int slot)
{
    constexpr int C = 64;
    __shared__ float sh_sum[C], sh_sq[C];
    for (int i = threadIdx.x; i < C; i += 256) { sh_sum[i] = 0.f; sh_sq[i] = 0.f; }
    __syncthreads();

    int dst = (blockIdx.x * 256 + threadIdx.x) >> 5;
    int lane = threadIdx.x & 31;

    if (dst < N) {
        int beg = g_off[dst], end = g_off[dst + 1];
        float ad = adbuf[dst];
        float accx = 0.f, accy = 0.f;
        float m = -INFINITY, den = 0.f;

        for (int chunk = beg; chunk < end; chunk += 32) {
            int idx = chunk + lane;
            bool valid = idx < end;
            int src = valid ? g_csr[idx] : 0;
            float e = valid ? leaky02(asbuf[src] + ad) : -INFINITY;
            float cm = e;
            #pragma unroll
            for (int o = 16; o; o >>= 1) cm = fmaxf(cm, __shfl_xor_sync(0xffffffffu, cm, o));
            float mn = fmaxf(m, cm);
            float scale = __expf(m - mn);
            den *= scale;
            accx *= scale; accy *= scale;
            float ex = valid ? __expf(e - mn) : 0.f;
            float cs = ex;
            #pragma unroll
            for (int o = 16; o; o >>= 1) cs += __shfl_xor_sync(0xffffffffu, cs, o);
            den += cs;

            int cnt = min(32, end - chunk);
            int i = 0;
            for (; i + 4 <= cnt; i += 4) {
                int   s0 = __shfl_sync(0xffffffffu, src, i + 0);
                int   s1 = __shfl_sync(0xffffffffu, src, i + 1);
                int   s2 = __shfl_sync(0xffffffffu, src, i + 2);
                int   s3 = __shfl_sync(0xffffffffu, src, i + 3);
                float w0 = __shfl_sync(0xffffffffu, ex,  i + 0);
                float w1 = __shfl_sync(0xffffffffu, ex,  i + 1);
                float w2 = __shfl_sync(0xffffffffu, ex,  i + 2);
                float w3 = __shfl_sync(0xffffffffu, ex,  i + 3);
                float2 f0 = *(const float2*)&h[(size_t)s0 * C + 2 * lane];
                float2 f1 = *(const float2*)&h[(size_t)s1 * C + 2 * lane];
                float2 f2 = *(const float2*)&h[(size_t)s2 * C + 2 * lane];
                float2 f3 = *(const float2*)&h[(size_t)s3 * C + 2 * lane];
                accx += w0 * f0.x + w1 * f1.x + w2 * f2.x + w3 * f3.x;
                accy += w0 * f0.y + w1 * f1.y + w2 * f2.y + w3 * f3.y;
            }
            for (; i < cnt; i++) {
                int   s0 = __shfl_sync(0xffffffffu, src, i);
                float w0 = __shfl_sync(0xffffffffu, ex,  i);
                float2 f0 = *(const float2*)&h[(size_t)s0 * C + 2 * lane];
                accx += w0 * f0.x;
                accy += w0 * f0.y;
            }
            m = mn;
        }
        float inv = 1.f / (den + 1e-16f);
        float ox = accx * inv, oy = accy * inv;
        *(float2*)&out[(size_t)dst * C + 2 * lane] = make_float2(ox, oy);
        atomicAdd(&sh_sum[2 * lane], ox);     atomicAdd(&sh_sq[2 * lane], ox * ox);
        atomicAdd(&sh_sum[2 * lane + 1], oy); atomicAdd(&sh_sq[2 * lane + 1], oy * oy);
    }
    __syncthreads();
    for (int i = threadIdx.x; i < C; i += 256) {
        atomicAdd(&g_bnsum[slot][i], sh_sum[i]);
        atomicAdd(&g_bnsq[slot][i], sh_sq[i]);
    }
}

// ---------------- BN + ELU (+ optional fused pool) ----------------
__global__ void bn_elu_kernel(float* __restrict__ x, int N, int F, int slot,
                              const float* __restrict__ g, const float* __restrict__ bt,
                              const int* __restrict__ batch, int do_pool)
{
    int i = blockIdx.x * blockDim.x + threadIdx.x;
    if (i >= N * F) return;
    int f = i % F;
    float inv_n = 1.0f / (float)N;
    float mu = g_bnsum[slot][f] * inv_n;
    float var = g_bnsq[slot][f] * inv_n - mu * mu;
    float v = (x[i] - mu) * rsqrtf(var + 1e-5f) * g[f] + bt[f];
    v = v > 0.f ? v : (expf(v) - 1.f);
    x[i] = v;
    if (do_pool) {
        int n = i / F;
        int b = batch[n];
        atomicAdd(&g_pool[b * 64 + f], v);
        if (f == 0) atomicAdd(&g_cnt[b], 1.0f);
    }
}

// ---------------- MLP head ----------------
__global__ void mlp_kernel(const float* __restrict__ fw1, const float* __restrict__ fb1,
                           const float* __restrict__ fw2, const float* __restrict__ fb2,
                           const float* __restrict__ fw3, const float* __restrict__ fb3,
                           float* __restrict__ out)
{
    __shared__ float p[64], z1[128], z2[32];
    int gph = blockIdx.x;
    int t = threadIdx.x;
    if (t < 64) p[t] = g_pool[gph * 64 + t] / fmaxf(g_cnt[gph], 1.0f);
    __syncthreads();
    float a = fb1[t];
    #pragma unroll 8
    for (int k = 0; k < 64; k++) a += p[k] * fw1[k * 128 + t];
    z1[t] = leaky02(a);
    __syncthreads();
    if (t < 32) {
        float b = fb2[t];
        #pragma unroll 8
        for (int k = 0; k < 128; k++) b += z1[k] * fw2[k * 32 + t];
        z2[t] = leaky02(b);
    }
    __syncthreads();
    if (t < 2) {
        float c = fb3[t];
        #pragma unroll
        for (int k = 0; k < 32; k++) c += z2[k] * fw3[k * 2 + t];
        out[gph * 2 + t] = c;
    }
}

// ---------------- host orchestration ----------------
static const int GEMM_DYN_SMEM = (8192 + 2 * 2304) * 4;

extern "C" void kernel_launch(void* const* d_in, const int* in_sizes, int n_in,
                              void* d_out, int out_size)
{
    const float* x     = (const float*)d_in[0];
    const int*   ei    = (const int*)  d_in[1];
    const int*   batch = (const int*)  d_in[2];
    const float* W1  = (const float*)d_in[3];
    const float* as1 = (const float*)d_in[4];
    const float* ad1 = (const float*)d_in[5];
    const float* W2  = (const float*)d_in[7];
    const float* as2 = (const float*)d_in[8];
    const float* ad2 = (const float*)d_in[9];
    const float* W3  = (const float*)d_in[11];
    const float* as3 = (const float*)d_in[12];
    const float* ad3 = (const float*)d_in[13];
    const float* g1  = (const float*)d_in[15];
    const float* bt1 = (const float*)d_in[16];
    const float* g2  = (const float*)d_in[17];
    const float* bt2 = (const float*)d_in[18];
    const float* g3  = (const float*)d_in[19];
    const float* bt3 = (const float*)d_in[20];
    const float* fw1 = (const float*)d_in[21];
    const float* fb1 = (const float*)d_in[22];
    const float* fw2 = (const float*)d_in[23];
    const float* fb2 = (const float*)d_in[24];
    const float* fw3 = (const float*)d_in[25];
    const float* fb3 = (const float*)d_in[26];

    int N = in_sizes[0] / 128;
    int E = in_sizes[1] / 2;
    int nb = (N + 255) / 256;

    cudaFuncSetAttribute(gemm_tc_kernel, cudaFuncAttributeMaxDynamicSharedMemorySize,
                         GEMM_DYN_SMEM);

    float *hbuf, *obuf;
    cudaGetSymbolAddress((void**)&hbuf, g_h);
    cudaGetSymbolAddress((void**)&obuf, g_out);
    float *pas1, *pad1, *pas2, *pad2, *pas3, *pad3;
    cudaGetSymbolAddress((void**)&pas1, g_as1);
    cudaGetSymbolAddress((void**)&pad1, g_ad1);
    cudaGetSymbolAddress((void**)&pas2, g_as2);
    cudaGetSymbolAddress((void**)&pad2, g_ad2);
    cudaGetSymbolAddress((void**)&pas3, g_as3);
    cudaGetSymbolAddress((void**)&pad3, g_ad3);

    // --- CSR build: 5 launches, so the first GEMM lands in ncu's -s 5 slot ---
    init_once_kernel<<<(N * 4 + 255) / 256, 256>>>(N);
    count_kernel<<<(E + 255) / 256, 256>>>(ei, E);
    partialscan_kernel<<<nb, 256>>>(N, nb);
    off_kernel<<<nb, 256>>>(N);
    loopscatter_kernel<<<(N + E + 255) / 256, 256>>>(ei, N, E);

    int aggblocks = (N + 7) / 8;

    // ---- layer 1: 128 -> 4x64
    {
        dim3 gb(256 / 64, (N + 127) / 128);
        gemm_tc_kernel<<<gb, 128, GEMM_DYN_SMEM>>>(x, W1, hbuf, N, 128, 256, as1, ad1, 64,
                                                   pas1, pad1);
        aggregateH4_kernel<64><<<aggblocks, 256>>>(hbuf, obuf, N, (const float4*)pas1,
                                                   (const float4*)pad1, 0);
        bn_elu_kernel<<<(N * 256 + 255) / 256, 256>>>(obuf, N, 256, 0, g1, bt1, batch, 0);
    }
    // ---- layer 2: 256 -> 4x32
    {
        dim3 gb(128 / 64, (N + 127) / 128);
        gemm_tc_kernel<<<gb, 128, GEMM_DYN_SMEM>>>(obuf, W2, hbuf, N, 256, 128, as2, ad2, 32,
                                                   pas2, pad2);
        aggregateH4_kernel<32><<<aggblocks, 256>>>(hbuf, obuf, N, (const float4*)pas2,
                                                   (const float4*)pad2, 1);
        bn_elu_kernel<<<(N * 128 + 255) / 256, 256>>>(obuf, N, 128, 1, g2, bt2, batch, 0);
    }
    // ---- layer 3: 128 -> 1x64
    {
        dim3 gb(64 / 64, (N + 127) / 128);
        gemm_tc_kernel<<<gb, 128, GEMM_DYN_SMEM>>>(obuf, W3, hbuf, N, 128, 64, as3, ad3, 64,
                                                   pas3, pad3);
        aggregate64_kernel<<<aggblocks, 256>>>(hbuf, obuf, N, pas3, pad3, 2);
        bn_elu_kernel<<<(N * 64 + 255) / 256, 256>>>(obuf, N, 64, 2, g3, bt3, batch, 1);
    }

    mlp_kernel<<<64, 128>>>(fw1, fb1, fw2, fb2, fw3, fb3, (float*)d_out);
}

// round 17
// speedup vs baseline: 5.8626x; 1.0155x over previous
#include <cuda_runtime.h>
#include <math.h>

// ---------------- scratch (static device globals; no allocation) ----------------
__device__ float g_h  [50000 * 256];
__device__ float g_out[50000 * 256];
__device__ __align__(16) float g_as1[50000 * 4];
__device__ __align__(16) float g_ad1[50000 * 4];
__device__ __align__(16) float g_as2[50000 * 4];
__device__ __align__(16) float g_ad2[50000 * 4];
__device__ float g_as3[50000], g_ad3[50000];
__device__ int   g_deg[50000];
__device__ int   g_off[50001];
__device__ int   g_cur[50000];
__device__ int   g_csr[850000];
__device__ int   g_bsum[256];
__device__ int   g_tick;
__device__ __align__(16) float g_bnsum[3][256];
__device__ __align__(16) float g_bnsq [3][256];
__device__ float g_pool[64 * 64];
__device__ float g_cnt [64];

__device__ __forceinline__ float leaky02(float v) { return v > 0.f ? v : 0.2f * v; }

__device__ __forceinline__ unsigned f2tf32(float x) {
    unsigned r; asm("cvt.rna.tf32.f32 %0, %1;" : "=r"(r) : "f"(x)); return r;
}

__device__ __forceinline__ void mma_tf32(float* d, const unsigned* a, const unsigned* b) {
    asm volatile(
        "mma.sync.aligned.m16n8k8.row.col.f32.tf32.tf32.f32 "
        "{%0,%1,%2,%3}, {%4,%5,%6,%7}, {%8,%9}, {%0,%1,%2,%3};"
        : "+f"(d[0]), "+f"(d[1]), "+f"(d[2]), "+f"(d[3])
        : "r"(a[0]), "r"(a[1]), "r"(a[2]), "r"(a[3]), "r"(b[0]), "r"(b[1]));
}

// ---------------- launch 0: one-time init ----------------
__global__ void init_once_kernel(int N) {
    int i = blockIdx.x * blockDim.x + threadIdx.x;
    if (i < N) { g_deg[i] = 0; g_as3[i] = 0.f; g_ad3[i] = 0.f; }
    if (i < N * 4) { g_as1[i] = 0.f; g_ad1[i] = 0.f; g_as2[i] = 0.f; g_ad2[i] = 0.f; }
    if (i < 64 * 64) g_pool[i] = 0.f;
    if (i < 64) g_cnt[i] = 0.f;
    if (i < 256) {
        for (int l = 0; l < 3; l++) { g_bnsum[l][i] = 0.f; g_bnsq[l][i] = 0.f; }
    }
    if (i == 0) g_tick = 0;
}

// ---------------- launch 1: degree count ----------------
__global__ void count_kernel(const int* __restrict__ ei, int E) {
    int e = blockIdx.x * blockDim.x + threadIdx.x;
    if (e < E) atomicAdd(&g_deg[ei[E + e]], 1);
}

// ---------------- launch 2: block partials + last-block scan ----------------
__global__ void partialscan_kernel(int N, int nb) {
    __shared__ int sh[256];
    __shared__ int lastflag;
    int tid = threadIdx.x;
    int i = blockIdx.x * 256 + tid;
    sh[tid] = (i < N) ? (g_deg[i] + 1) : 0;
    __syncthreads();
    for (int o = 128; o; o >>= 1) {
        if (tid < o) sh[tid] += sh[tid + o];
        __syncthreads();
    }
    if (tid == 0) {
        g_bsum[blockIdx.x] = sh[0];
        __threadfence();
        int t = atomicAdd(&g_tick, 1);
        lastflag = (t == nb - 1);
    }
    __syncthreads();
    if (lastflag) {
        __threadfence();
        int v = (tid < nb) ? g_bsum[tid] : 0;
        sh[tid] = v;
        __syncthreads();
        for (int o = 1; o < 256; o <<= 1) {
            int t2 = (tid >= o) ? sh[tid - o] : 0;
            __syncthreads();
            sh[tid] += t2;
            __syncthreads();
        }
        if (tid < nb) g_bsum[tid] = sh[tid] - v;
    }
}

// ---------------- launch 3: per-node offsets (+ g_cur init) ----------------
__global__ void off_kernel(int N) {
    __shared__ int sh[256];
    int tid = threadIdx.x;
    int i = blockIdx.x * 256 + tid;
    int v = (i < N) ? (g_deg[i] + 1) : 0;
    sh[tid] = v;
    __syncthreads();
    for (int o = 1; o < 256; o <<= 1) {
        int t = (tid >= o) ? sh[tid - o] : 0;
        __syncthreads();
        sh[tid] += t;
        __syncthreads();
    }
    if (i < N) {
        g_off[i + 1] = g_bsum[blockIdx.x] + sh[tid];
        g_cur[i] = 0;
    }
    if (i == 0) g_off[0] = 0;
}

// ---------------- launch 4: self-loops + edge scatter ----------------
__global__ void loopscatter_kernel(const int* __restrict__ ei, int N, int E) {
    int i = blockIdx.x * blockDim.x + threadIdx.x;
    if (i < N) {
        g_csr[g_off[i]] = i;
    } else if (i < N + E) {
        int e = i - N;
        int d = ei[E + e];
        int pos = g_off[d] + 1 + atomicAdd(&g_cur[d], 1);
        g_csr[pos] = ei[e];
    }
}

// ---------------- TF32 TC GEMM; fused BN+ELU on A-load; fused score epilogue ----------------
// C[N,K] = elu(bn(A))[N,M] @ B[M,K]  (bn applied iff slot >= 0)
// BM=128, BN=64, BK=32; 128 threads = 4 warps, warp tile 64x32.
__global__ __launch_bounds__(128) void gemm_tc_kernel(
    const float* __restrict__ A, const float* __restrict__ B, float* __restrict__ C,
    int N, int M, int K,
    const float* __restrict__ atts, const float* __restrict__ attd, int Chead,
    float* __restrict__ asbuf, float* __restrict__ adbuf,
    int slot, const float* __restrict__ gamma, const float* __restrict__ beta, float invN)
{
    __shared__ unsigned As[128 * 32];
    __shared__ unsigned Bs[32 * 72];

    int t = threadIdx.x;
    int lane = t & 31;
    int wid = t >> 5;
    int g = lane >> 2;
    int q = lane & 3;
    int warpM = (wid >> 1) * 64;
    int warpN = (wid & 1) * 32;
    int row0 = blockIdx.y * 128;
    int col0 = blockIdx.x * 64;
    int Hh = K / Chead;

    float acc[4][4][4];
    #pragma unroll
    for (int i = 0; i < 4; i++)
        #pragma unroll
        for (int j = 0; j < 4; j++)
            #pragma unroll
            for (int r = 0; r < 4; r++) acc[i][j][r] = 0.f;

    for (int k0 = 0; k0 < M; k0 += 32) {
        // ---- A tile (with optional fused BN+ELU)
        #pragma unroll
        for (int s = 0; s < 8; s++) {
            int idx = t + s * 128;
            int r = idx >> 3;
            int k4 = (idx & 7) * 4;
            int gr = row0 + r;
            float4 v = make_float4(0.f, 0.f, 0.f, 0.f);
            if (gr < N) v = *(const float4*)&A[(size_t)gr * M + k0 + k4];
            if (slot >= 0) {
                int f = k0 + k4;
                float4 bs = *(const float4*)&g_bnsum[slot][f];
                float4 bq = *(const float4*)&g_bnsq[slot][f];
                float4 gm = *(const float4*)&gamma[f];
                float4 bt = *(const float4*)&beta[f];
                float mu, var, sc;
                mu = bs.x * invN; var = bq.x * invN - mu * mu;
                sc = gm.x * rsqrtf(var + 1e-5f);
                v.x = (v.x - mu) * sc + bt.x; v.x = v.x > 0.f ? v.x : (expf(v.x) - 1.f);
                mu = bs.y * invN; var = bq.y * invN - mu * mu;
                sc = gm.y * rsqrtf(var + 1e-5f);
                v.y = (v.y - mu) * sc + bt.y; v.y = v.y > 0.f ? v.y : (expf(v.y) - 1.f);
                mu = bs.z * invN; var = bq.z * invN - mu * mu;
                sc = gm.z * rsqrtf(var + 1e-5f);
                v.z = (v.z - mu) * sc + bt.z; v.z = v.z > 0.f ? v.z : (expf(v.z) - 1.f);
                mu = bs.w * invN; var = bq.w * invN - mu * mu;
                sc = gm.w * rsqrtf(var + 1e-5f);
                v.w = (v.w - mu) * sc + bt.w; v.w = v.w > 0.f ? v.w : (expf(v.w) - 1.f);
            }
            int sw = k4 ^ (4 * (r & 7));
            unsigned* p = &As[r * 32 + sw];
            p[0] = f2tf32(v.x); p[1] = f2tf32(v.y); p[2] = f2tf32(v.z); p[3] = f2tf32(v.w);
        }
        // ---- B tile
        #pragma unroll
        for (int s = 0; s < 4; s++) {
            int idx = t + s * 128;
            int k = idx >> 4;
            int n4 = (idx & 15) * 4;
            float4 v = *(const float4*)&B[(size_t)(k0 + k) * K + col0 + n4];
            unsigned* p = &Bs[k * 72 + n4];
            p[0] = f2tf32(v.x); p[1] = f2tf32(v.y); p[2] = f2tf32(v.z); p[3] = f2tf32(v.w);
        }
        __syncthreads();

        #pragma unroll
        for (int kk = 0; kk < 4; kk++) {
            int kb = kk * 8;
            unsigned a[4][4], b[4][2];
            #pragma unroll
            for (int ma = 0; ma < 4; ma++) {
                int r0 = warpM + ma * 16 + g;
                int r1 = r0 + 8;
                int swz = 4 * (r0 & 7);
                a[ma][0] = As[r0 * 32 + ((kb + q)     ^ swz)];
                a[ma][1] = As[r1 * 32 + ((kb + q)     ^ swz)];
                a[ma][2] = As[r0 * 32 + ((kb + q + 4) ^ swz)];
                a[ma][3] = As[r1 * 32 + ((kb + q + 4) ^ swz)];
            }
            #pragma unroll
            for (int na = 0; na < 4; na++) {
                int c = warpN + na * 8 + g;
                b[na][0] = Bs[(kb + q)     * 72 + c];
                b[na][1] = Bs[(kb + q + 4) * 72 + c];
            }
            #pragma unroll
            for (int ma = 0; ma < 4; ma++)
                #pragma unroll
                for (int na = 0; na < 4; na++)
                    mma_tf32(acc[ma][na], a[ma], b[na]);
        }
        __syncthreads();
    }

    int headw = (col0 + warpN) / Chead;
    int basec = (col0 + warpN) % Chead;
    const float* av = atts + headw * Chead;
    const float* dv = attd + headw * Chead;

    #pragma unroll
    for (int ma = 0; ma < 4; ma++) {
        int r0 = row0 + warpM + ma * 16 + g;
        int r1 = r0 + 8;
        float s0 = 0.f, d0 = 0.f, s1 = 0.f, d1 = 0.f;
        #pragma unroll
        for (int na = 0; na < 4; na++) {
            int c = col0 + warpN + na * 8 + 2 * q;
            int ch = basec + na * 8 + 2 * q;
            float a0 = av[ch], a1 = av[ch + 1];
            float b0 = dv[ch], b1 = dv[ch + 1];
            if (r0 < N) {
                float2 v0 = make_float2(acc[ma][na][0], acc[ma][na][1]);
                *(float2*)&C[(size_t)r0 * K + c] = v0;
                s0 += v0.x * a0 + v0.y * a1;
                d0 += v0.x * b0 + v0.y * b1;
            }
            if (r1 < N) {
                float2 v1 = make_float2(acc[ma][na][2], acc[ma][na][3]);
                *(float2*)&C[(size_t)r1 * K + c] = v1;
                s1 += v1.x * a0 + v1.y * a1;
                d1 += v1.x * b0 + v1.y * b1;
            }
        }
        #pragma unroll
        for (int o = 1; o < 4; o <<= 1) {
            s0 += __shfl_xor_sync(0xffffffffu, s0, o);
            d0 += __shfl_xor_sync(0xffffffffu, d0, o);
            s1 += __shfl_xor_sync(0xffffffffu, s1, o);
            d1 += __shfl_xor_sync(0xffffffffu, d1, o);
        }
        if (q == 0) {
            if (r0 < N) { atomicAdd(&asbuf[r0 * Hh + headw], s0); atomicAdd(&adbuf[r0 * Hh + headw], d0); }
            if (r1 < N) { atomicAdd(&asbuf[r1 * Hh + headw], s1); atomicAdd(&adbuf[r1 * Hh + headw], d1); }
        }
    }
}

// ---------------- merged-head aggregation (Hh=4), fused BN stats ----------------
template <int C>   // C = 64 (HC=256) or 32 (HC=128)
__global__ void aggregateH4_kernel(const float* __restrict__ h, float* __restrict__ out,
                                   int N,
                                   const float4* __restrict__ as4,
                                   const float4* __restrict__ ad4, int slot)
{
    constexpr int HC = 4 * C;
    constexpr int NV = HC / 128;
    __shared__ float sh_sum[HC], sh_sq[HC];
    for (int i = threadIdx.x; i < HC; i += 256) { sh_sum[i] = 0.f; sh_sq[i] = 0.f; }
    __syncthreads();

    int dst = (blockIdx.x * 256 + threadIdx.x) >> 5;
    int lane = threadIdx.x & 31;

    if (dst < N) {
        int beg = g_off[dst], end = g_off[dst + 1];
        float4 adv = ad4[dst];
        float acc[NV][4];
        #pragma unroll
        for (int v = 0; v < NV; v++)
            #pragma unroll
            for (int j = 0; j < 4; j++) acc[v][j] = 0.f;
        float m[4]   = {-INFINITY, -INFINITY, -INFINITY, -INFINITY};
        float den[4] = {0.f, 0.f, 0.f, 0.f};
        int hv[NV];
        #pragma unroll
        for (int v = 0; v < NV; v++) hv[v] = (v * 128 + lane * 4) / C;

        for (int chunk = beg; chunk < end; chunk += 32) {
            int idx = chunk + lane;
            bool valid = idx < end;
            int src = valid ? g_csr[idx] : 0;
            float4 sv = as4[src];
            float e[4];
            e[0] = valid ? leaky02(sv.x + adv.x) : -INFINITY;
            e[1] = valid ? leaky02(sv.y + adv.y) : -INFINITY;
            e[2] = valid ? leaky02(sv.z + adv.z) : -INFINITY;
            e[3] = valid ? leaky02(sv.w + adv.w) : -INFINITY;

            float ex[4], scale[4];
            #pragma unroll
            for (int hh = 0; hh < 4; hh++) {
                float cm = e[hh];
                #pragma unroll
                for (int o = 16; o; o >>= 1) cm = fmaxf(cm, __shfl_xor_sync(0xffffffffu, cm, o));
                float mn = fmaxf(m[hh], cm);
                scale[hh] = __expf(m[hh] - mn);
                den[hh] *= scale[hh];
                ex[hh] = valid ? __expf(e[hh] - mn) : 0.f;
                float cs = ex[hh];
                #pragma unroll
                for (int o = 16; o; o >>= 1) cs += __shfl_xor_sync(0xffffffffu, cs, o);
                den[hh] += cs;
                m[hh] = mn;
            }
            #pragma unroll
            for (int v = 0; v < NV; v++) {
                float s = scale[hv[v]];
                #pragma unroll
                for (int j = 0; j < 4; j++) acc[v][j] *= s;
            }

            int cnt = min(32, end - chunk);
            if (C == 64) {
                int i = 0;
                for (; i + 2 <= cnt; i += 2) {
                    int sA = __shfl_sync(0xffffffffu, src, i);
                    int sB = __shfl_sync(0xffffffffu, src, i + 1);
                    float a0 = __shfl_sync(0xffffffffu, ex[0], i);
                    float a1 = __shfl_sync(0xffffffffu, ex[1], i);
                    float a2 = __shfl_sync(0xffffffffu, ex[2], i);
                    float a3 = __shfl_sync(0xffffffffu, ex[3], i);
                    float b0 = __shfl_sync(0xffffffffu, ex[0], i + 1);
                    float b1 = __shfl_sync(0xffffffffu, ex[1], i + 1);
                    float b2 = __shfl_sync(0xffffffffu, ex[2], i + 1);
                    float b3 = __shfl_sync(0xffffffffu, ex[3], i + 1);
                    bool hi = lane >= 16;
                    float wA0 = hi ? a1 : a0, wA1 = hi ? a3 : a2;
                    float wB0 = hi ? b1 : b0, wB1 = hi ? b3 : b2;
                    const float4* pA = (const float4*)(h + (size_t)sA * 256);
                    const float4* pB = (const float4*)(h + (size_t)sB * 256);
                    float4 fA0 = pA[lane], fA1 = pA[32 + lane];
                    float4 fB0 = pB[lane], fB1 = pB[32 + lane];
                    acc[0][0] += wA0 * fA0.x + wB0 * fB0.x;
                    acc[0][1] += wA0 * fA0.y + wB0 * fB0.y;
                    acc[0][2] += wA0 * fA0.z + wB0 * fB0.z;
                    acc[0][3] += wA0 * fA0.w + wB0 * fB0.w;
                    acc[NV-1][0] += wA1 * fA1.x + wB1 * fB1.x;
                    acc[NV-1][1] += wA1 * fA1.y + wB1 * fB1.y;
                    acc[NV-1][2] += wA1 * fA1.z + wB1 * fB1.z;
                    acc[NV-1][3] += wA1 * fA1.w + wB1 * fB1.w;
                }
                for (; i < cnt; i++) {
                    int sA = __shfl_sync(0xffffffffu, src, i);
                    float a0 = __shfl_sync(0xffffffffu, ex[0], i);
                    float a1 = __shfl_sync(0xffffffffu, ex[1], i);
                    float a2 = __shfl_sync(0xffffffffu, ex[2], i);
                    float a3 = __shfl_sync(0xffffffffu, ex[3], i);
                    bool hi = lane >= 16;
                    float wA0 = hi ? a1 : a0, wA1 = hi ? a3 : a2;
                    const float4* pA = (const float4*)(h + (size_t)sA * 256);
                    float4 fA0 = pA[lane], fA1 = pA[32 + lane];
                    acc[0][0] += wA0 * fA0.x;
                    acc[0][1] += wA0 * fA0.y;
                    acc[0][2] += wA0 * fA0.z;
                    acc[0][3] += wA0 * fA0.w;
                    acc[NV-1][0] += wA1 * fA1.x;
                    acc[NV-1][1] += wA1 * fA1.y;
                    acc[NV-1][2] += wA1 * fA1.z;
                    acc[NV-1][3] += wA1 * fA1.w;
                }
            } else {
                int hh0 = lane >> 3;
                int i = 0;
                for (; i + 2 <= cnt; i += 2) {
                    int sA = __shfl_sync(0xffffffffu, src, i);
                    int sB = __shfl_sync(0xffffffffu, src, i + 1);
                    float a0 = __shfl_sync(0xffffffffu, ex[0], i);
                    float a1 = __shfl_sync(0xffffffffu, ex[1], i);
                    float a2 = __shfl_sync(0xffffffffu, ex[2], i);
                    float a3 = __shfl_sync(0xffffffffu, ex[3], i);
                    float b0 = __shfl_sync(0xffffffffu, ex[0], i + 1);
                    float b1 = __shfl_sync(0xffffffffu, ex[1], i + 1);
                    float b2 = __shfl_sync(0xffffffffu, ex[2], i + 1);
                    float b3 = __shfl_sync(0xffffffffu, ex[3], i + 1);
                    float wA = hh0 < 2 ? (hh0 == 0 ? a0 : a1) : (hh0 == 2 ? a2 : a3);
                    float wB = hh0 < 2 ? (hh0 == 0 ? b0 : b1) : (hh0 == 2 ? b2 : b3);
                    float4 fA = ((const float4*)(h + (size_t)sA * 128))[lane];
                    float4 fB = ((const float4*)(h + (size_t)sB * 128))[lane];
                    acc[0][0] += wA * fA.x + wB * fB.x;
                    acc[0][1] += wA * fA.y + wB * fB.y;
                    acc[0][2] += wA * fA.z + wB * fB.z;
                    acc[0][3] += wA * fA.w + wB * fB.w;
                }
                for (; i < cnt; i++) {
                    int sA = __shfl_sync(0xffffffffu, src, i);
                    float a0 = __shfl_sync(0xffffffffu, ex[0], i);
                    float a1 = __shfl_sync(0xffffffffu, ex[1], i);
                    float a2 = __shfl_sync(0xffffffffu, ex[2], i);
                    float a3 = __shfl_sync(0xffffffffu, ex[3], i);
                    float wA = hh0 < 2 ? (hh0 == 0 ? a0 : a1) : (hh0 == 2 ? a2 : a3);
                    float4 fA = ((const float4*)(h + (size_t)sA * 128))[lane];
                    acc[0][0] += wA * fA.x;
                    acc[0][1] += wA * fA.y;
                    acc[0][2] += wA * fA.z;
                    acc[0][3] += wA * fA.w;
                }
            }
        }

        #pragma unroll
        for (int v = 0; v < NV; v++) {
            float inv = 1.f / (den[hv[v]] + 1e-16f);
            float4 o4;
            o4.x = acc[v][0] * inv; o4.y = acc[v][1] * inv;
            o4.z = acc[v][2] * inv; o4.w = acc[v][3] * inv;
            int cb = v * 128 + lane * 4;
            *(float4*)&out[(size_t)dst * HC + cb] = o4;
            atomicAdd(&sh_sum[cb + 0], o4.x); atomicAdd(&sh_sq[cb + 0], o4.x * o4.x);
            atomicAdd(&sh_sum[cb + 1], o4.y); atomicAdd(&sh_sq[cb + 1], o4.y * o4.y);
            atomicAdd(&sh_sum[cb + 2], o4.z); atomicAdd(&sh_sq[cb + 2], o4.z * o4.z);
            atomicAdd(&sh_sum[cb + 3], o4.w); atomicAdd(&sh_sq[cb + 3], o4.w * o4.w);
        }
    }
    __syncthreads();
    for (int i = threadIdx.x; i < HC; i += 256) {
        atomicAdd(&g_bnsum[slot][i], sh_sum[i]);
        atomicAdd(&g_bnsq[slot][i], sh_sq[i]);
    }
}

// ---------------- aggregation for Hh=1, C=64 (layer 3), fused BN stats ----------------
__global__ void aggregate64_kernel(const float* __restrict__ h, float* __restrict__ out,
                                   int N,
                                   const float* __restrict__ asbuf, const float* __restrict__ adbuf,
                                   int slot)
{
    constexpr int C = 64;
    __shared__ float sh_sum[C], sh_sq[C];
    for (int i = threadIdx.x; i < C; i += 256) { sh_sum[i] = 0.f; sh_sq[i] = 0.f; }
    __syncthreads();

    int dst = (blockIdx.x * 256 + threadIdx.x) >> 5;
    int lane = threadIdx.x & 31;

    if (dst < N) {
        int beg = g_off[dst], end = g_off[dst + 1];
        float ad = adbuf[dst];
        float accx = 0.f, accy = 0.f;
        float m = -INFINITY, den = 0.f;

        for (int chunk = beg; chunk < end; chunk += 32) {
            int idx = chunk + lane;
            bool valid = idx < end;
            int src = valid ? g_csr[idx] : 0;
            float e = valid ? leaky02(asbuf[src] + ad) : -INFINITY;
            float cm = e;
            #pragma unroll
            for (int o = 16; o; o >>= 1) cm = fmaxf(cm, __shfl_xor_sync(0xffffffffu, cm, o));
            float mn = fmaxf(m, cm);
            float scale = __expf(m - mn);
            den *= scale;
            accx *= scale; accy *= scale;
            float ex = valid ? __expf(e - mn) : 0.f;
            float cs = ex;
            #pragma unroll
            for (int o = 16; o; o >>= 1) cs += __shfl_xor_sync(0xffffffffu, cs, o);
            den += cs;

            int cnt = min(32, end - chunk);
            int i = 0;
            for (; i + 4 <= cnt; i += 4) {
                int   s0 = __shfl_sync(0xffffffffu, src, i + 0);
                int   s1 = __shfl_sync(0xffffffffu, src, i + 1);
                int   s2 = __shfl_sync(0xffffffffu, src, i + 2);
                int   s3 = __shfl_sync(0xffffffffu, src, i + 3);
                float w0 = __shfl_sync(0xffffffffu, ex,  i + 0);
                float w1 = __shfl_sync(0xffffffffu, ex,  i + 1);
                float w2 = __shfl_sync(0xffffffffu, ex,  i + 2);
                float w3 = __shfl_sync(0xffffffffu, ex,  i + 3);
                float2 f0 = *(const float2*)&h[(size_t)s0 * C + 2 * lane];
                float2 f1 = *(const float2*)&h[(size_t)s1 * C + 2 * lane];
                float2 f2 = *(const float2*)&h[(size_t)s2 * C + 2 * lane];
                float2 f3 = *(const float2*)&h[(size_t)s3 * C + 2 * lane];
                accx += w0 * f0.x + w1 * f1.x + w2 * f2.x + w3 * f3.x;
                accy += w0 * f0.y + w1 * f1.y + w2 * f2.y + w3 * f3.y;
            }
            for (; i < cnt; i++) {
                int   s0 = __shfl_sync(0xffffffffu, src, i);
                float w0 = __shfl_sync(0xffffffffu, ex,  i);
                float2 f0 = *(const float2*)&h[(size_t)s0 * C + 2 * lane];
                accx += w0 * f0.x;
                accy += w0 * f0.y;
            }
            m = mn;
        }
        float inv = 1.f / (den + 1e-16f);
        float ox = accx * inv, oy = accy * inv;
        *(float2*)&out[(size_t)dst * C + 2 * lane] = make_float2(ox, oy);
        atomicAdd(&sh_sum[2 * lane], ox);     atomicAdd(&sh_sq[2 * lane], ox * ox);
        atomicAdd(&sh_sum[2 * lane + 1], oy); atomicAdd(&sh_sq[2 * lane + 1], oy * oy);
    }
    __syncthreads();
    for (int i = threadIdx.x; i < C; i += 256) {
        atomicAdd(&g_bnsum[slot][i], sh_sum[i]);
        atomicAdd(&g_bnsq[slot][i], sh_sq[i]);
    }
}

// ---------------- BN + ELU + fused pool (layer 3 only) ----------------
__global__ void bn_elu_pool_kernel(const float* __restrict__ x, int N, int F, int slot,
                                   const float* __restrict__ g, const float* __restrict__ bt,
                                   const int* __restrict__ batch)
{
    int i = blockIdx.x * blockDim.x + threadIdx.x;
    if (i >= N * F) return;
    int f = i % F;
    float inv_n = 1.0f / (float)N;
    float mu = g_bnsum[slot][f] * inv_n;
    float var = g_bnsq[slot][f] * inv_n - mu * mu;
    float v = (x[i] - mu) * rsqrtf(var + 1e-5f) * g[f] + bt[f];
    v = v > 0.f ? v : (expf(v) - 1.f);
    int n = i / F;
    int b = batch[n];
    atomicAdd(&g_pool[b * 64 + f], v);
    if (f == 0) atomicAdd(&g_cnt[b], 1.0f);
}

// ---------------- MLP head ----------------
__global__ void mlp_kernel(const float* __restrict__ fw1, const float* __restrict__ fb1,
                           const float* __restrict__ fw2, const float* __restrict__ fb2,
                           const float* __restrict__ fw3, const float* __restrict__ fb3,
                           float* __restrict__ out)
{
    __shared__ float p[64], z1[128], z2[32];
    int gph = blockIdx.x;
    int t = threadIdx.x;
    if (t < 64) p[t] = g_pool[gph * 64 + t] / fmaxf(g_cnt[gph], 1.0f);
    __syncthreads();
    float a = fb1[t];
    #pragma unroll 8
    for (int k = 0; k < 64; k++) a += p[k] * fw1[k * 128 + t];
    z1[t] = leaky02(a);
    __syncthreads();
    if (t < 32) {
        float b = fb2[t];
        #pragma unroll 8
        for (int k = 0; k < 128; k++) b += z1[k] * fw2[k * 32 + t];
        z2[t] = leaky02(b);
    }
    __syncthreads();
    if (t < 2) {
        float c = fb3[t];
        #pragma unroll
        for (int k = 0; k < 32; k++) c += z2[k] * fw3[k * 2 + t];
        out[gph * 2 + t] = c;
    }
}

// ---------------- host orchestration ----------------
extern "C" void kernel_launch(void* const* d_in, const int* in_sizes, int n_in,
                              void* d_out, int out_size)
{
    const float* x     = (const float*)d_in[0];
    const int*   ei    = (const int*)  d_in[1];
    const int*   batch = (const int*)  d_in[2];
    const float* W1  = (const float*)d_in[3];
    const float* as1 = (const float*)d_in[4];
    const float* ad1 = (const float*)d_in[5];
    const float* W2  = (const float*)d_in[7];
    const float* as2 = (const float*)d_in[8];
    const float* ad2 = (const float*)d_in[9];
    const float* W3  = (const float*)d_in[11];
    const float* as3 = (const float*)d_in[12];
    const float* ad3 = (const float*)d_in[13];
    const float* g1  = (const float*)d_in[15];
    const float* bt1 = (const float*)d_in[16];
    const float* g2  = (const float*)d_in[17];
    const float* bt2 = (const float*)d_in[18];
    const float* g3  = (const float*)d_in[19];
    const float* bt3 = (const float*)d_in[20];
    const float* fw1 = (const float*)d_in[21];
    const float* fb1 = (const float*)d_in[22];
    const float* fw2 = (const float*)d_in[23];
    const float* fb2 = (const float*)d_in[24];
    const float* fw3 = (const float*)d_in[25];
    const float* fb3 = (const float*)d_in[26];

    int N = in_sizes[0] / 128;
    int E = in_sizes[1] / 2;
    int nb = (N + 255) / 256;
    float invN = 1.0f / (float)N;

    float *hbuf, *obuf;
    cudaGetSymbolAddress((void**)&hbuf, g_h);
    cudaGetSymbolAddress((void**)&obuf, g_out);
    float *pas1, *pad1, *pas2, *pad2, *pas3, *pad3;
    cudaGetSymbolAddress((void**)&pas1, g_as1);
    cudaGetSymbolAddress((void**)&pad1, g_ad1);
    cudaGetSymbolAddress((void**)&pas2, g_as2);
    cudaGetSymbolAddress((void**)&pad2, g_ad2);
    cudaGetSymbolAddress((void**)&pas3, g_as3);
    cudaGetSymbolAddress((void**)&pad3, g_ad3);

    // --- CSR build: 5 launches, so the first GEMM lands in ncu's -s 5 slot ---
    init_once_kernel<<<(N * 4 + 255) / 256, 256>>>(N);
    count_kernel<<<(E + 255) / 256, 256>>>(ei, E);
    partialscan_kernel<<<nb, 256>>>(N, nb);
    off_kernel<<<nb, 256>>>(N);
    loopscatter_kernel<<<(N + E + 255) / 256, 256>>>(ei, N, E);

    int aggblocks = (N + 7) / 8;

    // ---- layer 1: 128 -> 4x64 (no BN on input)
    {
        dim3 gb(256 / 64, (N + 127) / 128);
        gemm_tc_kernel<<<gb, 128>>>(x, W1, hbuf, N, 128, 256, as1, ad1, 64,
                                    pas1, pad1, -1, nullptr, nullptr, invN);
        aggregateH4_kernel<64><<<aggblocks, 256>>>(hbuf, obuf, N, (const float4*)pas1,
                                                   (const float4*)pad1, 0);
    }
    // ---- layer 2: 256 -> 4x32 (BN/ELU of layer-1 output fused into A-load)
    {
        dim3 gb(128 / 64, (N + 127) / 128);
        gemm_tc_kernel<<<gb, 128>>>(obuf, W2, hbuf, N, 256, 128, as2, ad2, 32,
                                    pas2, pad2, 0, g1, bt1, invN);
        aggregateH4_kernel<32><<<aggblocks, 256>>>(hbuf, obuf, N, (const float4*)pas2,
                                                   (const float4*)pad2, 1);
    }
    // ---- layer 3: 128 -> 1x64 (BN/ELU of layer-2 output fused into A-load)
    {
        dim3 gb(64 / 64, (N + 127) / 128);
        gemm_tc_kernel<<<gb, 128>>>(obuf, W3, hbuf, N, 128, 64, as3, ad3, 64,
                                    pas3, pad3, 1, g2, bt2, invN);
        aggregate64_kernel<<<aggblocks, 256>>>(hbuf, obuf, N, pas3, pad3, 2);
    }
    // ---- final BN + ELU + pool, then MLP
    bn_elu_pool_kernel<<<(N * 64 + 255) / 256, 256>>>(obuf, N, 64, 2, g3, bt3, batch);
    mlp_kernel<<<64, 128>>>(fw1, fb1, fw2, fb2, fw3, fb3, (float*)d_out);
}